// round 1
// baseline (speedup 1.0000x reference)
#include <cuda_runtime.h>
#include <cuda_bf16.h>

// Problem constants
constexpr int SEQ = 2048;
constexpr int NB  = 2;      // batch
constexpr int CH  = 1024;   // channels
constexpr int NH  = 16;     // heads
constexpr int CC  = 64;     // channels per head
constexpr int EPQ = 32;     // edges per query
constexpr int NE  = SEQ * EPQ;          // 65536 edges
constexpr int MROWS = SEQ * NB;         // 4096 GEMM rows
constexpr int EDGE_ELEMS = NE * NB * NH; // 2,097,152
constexpr int EDGE_BLOCKS = EDGE_ELEMS / 256; // 8192

// -------- device scratch (no allocations allowed) --------
__device__ float g_q[SEQ * NB * CH];
__device__ float g_k[SEQ * NB * CH];
__device__ float g_v[SEQ * NB * CH];
__device__ float g_attn[SEQ * NB * CH];
__device__ float g_qk[EDGE_ELEMS];
__device__ float g_pmax[EDGE_BLOCKS];
__device__ float g_max;

// ============================================================
// SGEMM with bias:  out[m,n] = sum_k A[m,k]*W[n,k] + bias[n]
// A: [M,K] row-major, W: [N,K] row-major (torch Linear weight)
// 128x128x8 tile, 256 threads, 8x8 per thread
// ============================================================
__global__ __launch_bounds__(256) void sgemm_bias_kernel(
    const float* __restrict__ A, const float* __restrict__ W,
    const float* __restrict__ bias, float* __restrict__ out,
    int M, int N, int K)
{
    constexpr int BM = 128, BN = 128, BK = 8, TM = 8, TN = 8;
    __shared__ float As[BK][BM];
    __shared__ float Bs[BK][BN];

    const int bm = blockIdx.y * BM;
    const int bn = blockIdx.x * BN;
    const int tid = threadIdx.x;
    const int tx = tid % 16;       // 0..15  (N direction)
    const int ty = tid / 16;       // 0..15  (M direction)

    // load mapping: each thread loads one float4 of A and one of W per k-block
    const int lr = tid >> 1;          // row 0..127
    const int lk = (tid & 1) * 4;     // k offset 0 or 4

    float acc[TM][TN];
    #pragma unroll
    for (int i = 0; i < TM; i++)
        #pragma unroll
        for (int j = 0; j < TN; j++) acc[i][j] = 0.0f;

    const float* Ap = A + (size_t)(bm + lr) * K + lk;
    const float* Wp = W + (size_t)(bn + lr) * K + lk;

    for (int k0 = 0; k0 < K; k0 += BK) {
        float4 av = *(const float4*)(Ap + k0);
        float4 wv = *(const float4*)(Wp + k0);
        As[lk + 0][lr] = av.x; As[lk + 1][lr] = av.y;
        As[lk + 2][lr] = av.z; As[lk + 3][lr] = av.w;
        Bs[lk + 0][lr] = wv.x; Bs[lk + 1][lr] = wv.y;
        Bs[lk + 2][lr] = wv.z; Bs[lk + 3][lr] = wv.w;
        __syncthreads();

        #pragma unroll
        for (int kk = 0; kk < BK; kk++) {
            float a[TM], b[TN];
            float4 a0 = *(const float4*)&As[kk][ty * TM];
            float4 a1 = *(const float4*)&As[kk][ty * TM + 4];
            a[0]=a0.x; a[1]=a0.y; a[2]=a0.z; a[3]=a0.w;
            a[4]=a1.x; a[5]=a1.y; a[6]=a1.z; a[7]=a1.w;
            float4 b0 = *(const float4*)&Bs[kk][tx * TN];
            float4 b1 = *(const float4*)&Bs[kk][tx * TN + 4];
            b[0]=b0.x; b[1]=b0.y; b[2]=b0.z; b[3]=b0.w;
            b[4]=b1.x; b[5]=b1.y; b[6]=b1.z; b[7]=b1.w;
            #pragma unroll
            for (int i = 0; i < TM; i++)
                #pragma unroll
                for (int j = 0; j < TN; j++)
                    acc[i][j] += a[i] * b[j];
        }
        __syncthreads();
    }

    #pragma unroll
    for (int i = 0; i < TM; i++) {
        const int row = bm + ty * TM + i;
        #pragma unroll
        for (int j = 0; j < TN; j += 4) {
            const int col = bn + tx * TN + j;
            float4 o;
            o.x = acc[i][j + 0] + bias[col + 0];
            o.y = acc[i][j + 1] + bias[col + 1];
            o.z = acc[i][j + 2] + bias[col + 2];
            o.w = acc[i][j + 3] + bias[col + 3];
            *(float4*)(out + (size_t)row * N + col) = o;
        }
    }
}

// ============================================================
// Per-edge scaled dot products + per-block max
// one thread per (e, b, h); qk layout [e][b][h]
// ============================================================
__global__ __launch_bounds__(256) void edge_qk_kernel(
    const float* __restrict__ q, const float* __restrict__ k,
    const int* __restrict__ q_id, const int* __restrict__ k_id,
    float* __restrict__ qk, float* __restrict__ pmax)
{
    const int idx = blockIdx.x * 256 + threadIdx.x;   // < NE*NB*NH
    const int h = idx & (NH - 1);
    const int b = (idx >> 4) & (NB - 1);
    const int e = idx >> 5;

    const int qs = q_id[e];
    const int ks = k_id[e];
    const float4* qp = (const float4*)(q + (size_t)(((qs * NB + b) * NH + h)) * CC);
    const float4* kp = (const float4*)(k + (size_t)(((ks * NB + b) * NH + h)) * CC);

    float s = 0.0f;
    #pragma unroll
    for (int i = 0; i < CC / 4; i++) {
        float4 a = qp[i];
        float4 c = kp[i];
        s += a.x * c.x + a.y * c.y + a.z * c.z + a.w * c.w;
    }
    s *= 0.125f;   // 1/sqrt(64)
    qk[idx] = s;

    __shared__ float red[256];
    red[threadIdx.x] = s;
    __syncthreads();
    #pragma unroll
    for (int off = 128; off > 0; off >>= 1) {
        if (threadIdx.x < off)
            red[threadIdx.x] = fmaxf(red[threadIdx.x], red[threadIdx.x + off]);
        __syncthreads();
    }
    if (threadIdx.x == 0) pmax[blockIdx.x] = red[0];
}

// ============================================================
// final max over partials (single block, deterministic)
// ============================================================
__global__ __launch_bounds__(256) void reduce_max_kernel(
    const float* __restrict__ pmax, int n, float* __restrict__ gmax)
{
    __shared__ float red[256];
    float m = -3.0e38f;
    for (int i = threadIdx.x; i < n; i += 256) m = fmaxf(m, pmax[i]);
    red[threadIdx.x] = m;
    __syncthreads();
    #pragma unroll
    for (int off = 128; off > 0; off >>= 1) {
        if (threadIdx.x < off)
            red[threadIdx.x] = fmaxf(red[threadIdx.x], red[threadIdx.x + off]);
        __syncthreads();
    }
    if (threadIdx.x == 0) *gmax = red[0];
}

// ============================================================
// Segment softmax + weighted value aggregation.
// q_id = repeat(arange(S), 32) -> edges [32s, 32s+32) belong to query s:
// contiguous segments, no atomics. One warp per (s, b, h); lane covers 2
// channels of cc=64.
// ============================================================
__global__ __launch_bounds__(256) void aggregate_kernel(
    const float* __restrict__ qk, const float* __restrict__ v,
    const int* __restrict__ k_id, const float* __restrict__ gmax,
    float* __restrict__ attn)
{
    const int gtid = blockIdx.x * 256 + threadIdx.x;
    const int wid  = gtid >> 5;
    const int lane = gtid & 31;
    const int h = wid & (NH - 1);
    const int b = (wid >> 4) & (NB - 1);
    const int s = wid >> 5;

    const float mx = *gmax;
    float nx = 0.0f, ny = 0.0f, d = 0.0f;
    const int ebase = s * EPQ;

    #pragma unroll 4
    for (int j = 0; j < EPQ; j++) {
        const int e = ebase + j;
        const float w = expf(qk[(e * NB + b) * NH + h] - mx);
        d += w;
        const int ks = k_id[e];
        const float2 vv = *(const float2*)(
            v + (size_t)(((ks * NB + b) * NH + h)) * CC + lane * 2);
        nx += w * vv.x;
        ny += w * vv.y;
    }
    const float inv = 1.0f / d;
    *(float2*)(attn + (size_t)(((s * NB + b) * NH + h)) * CC + lane * 2)
        = make_float2(nx * inv, ny * inv);
}

// ============================================================
// host launcher (graph-capturable: kernel launches only)
// ============================================================
extern "C" void kernel_launch(void* const* d_in, const int* in_sizes, int n_in,
                              void* d_out, int out_size)
{
    const float* x   = (const float*)d_in[0];
    const int*  q_id = (const int*)d_in[1];
    const int*  k_id = (const int*)d_in[2];
    const float* Wq  = (const float*)d_in[3];
    const float* bq  = (const float*)d_in[4];
    const float* Wk  = (const float*)d_in[5];
    const float* bk  = (const float*)d_in[6];
    const float* Wv  = (const float*)d_in[7];
    const float* bv  = (const float*)d_in[8];
    const float* Wx  = (const float*)d_in[9];
    const float* bx  = (const float*)d_in[10];
    float* out = (float*)d_out;

    float *q, *k, *v, *attn, *qkbuf, *pmax, *gmax;
    cudaGetSymbolAddress((void**)&q,     g_q);
    cudaGetSymbolAddress((void**)&k,     g_k);
    cudaGetSymbolAddress((void**)&v,     g_v);
    cudaGetSymbolAddress((void**)&attn,  g_attn);
    cudaGetSymbolAddress((void**)&qkbuf, g_qk);
    cudaGetSymbolAddress((void**)&pmax,  g_pmax);
    cudaGetSymbolAddress((void**)&gmax,  g_max);

    const dim3 gemm_grid(CH / 128, MROWS / 128);   // (8, 32)

    // q/k/v projections
    sgemm_bias_kernel<<<gemm_grid, 256>>>(x, Wq, bq, q, MROWS, CH, CH);
    sgemm_bias_kernel<<<gemm_grid, 256>>>(x, Wk, bk, k, MROWS, CH, CH);
    sgemm_bias_kernel<<<gemm_grid, 256>>>(x, Wv, bv, v, MROWS, CH, CH);

    // per-edge dots + global max
    edge_qk_kernel<<<EDGE_BLOCKS, 256>>>(q, k, q_id, k_id, qkbuf, pmax);
    reduce_max_kernel<<<1, 256>>>(pmax, EDGE_BLOCKS, gmax);

    // segment softmax + V aggregation
    aggregate_kernel<<<EDGE_BLOCKS, 256>>>(qkbuf, v, k_id, gmax, attn);

    // output projection
    sgemm_bias_kernel<<<gemm_grid, 256>>>(attn, Wx, bx, out, MROWS, CH, CH);
}

// round 3
// speedup vs baseline: 2.6312x; 2.6312x over previous
#include <cuda_runtime.h>
#include <cuda_bf16.h>
#include <cstdint>

// Problem constants
constexpr int SEQ = 2048;
constexpr int NB  = 2;      // batch
constexpr int CH  = 1024;   // channels
constexpr int NH  = 16;     // heads
constexpr int CC  = 64;     // channels per head
constexpr int EPQ = 32;     // edges per query
constexpr int NE  = SEQ * EPQ;          // 65536 edges
constexpr int MROWS = SEQ * NB;         // 4096 GEMM rows
constexpr int QK_BLOCKS  = NE * NB / 8;         // 16384 (8 warps/block, warp per (e,b))
constexpr int AGG_BLOCKS = SEQ * NB * NH / 8;   // 8192  (warp per (s,b,h))

// -------- device scratch (no allocations allowed) --------
__device__ float g_q[SEQ * NB * CH];
__device__ float g_k[SEQ * NB * CH];
__device__ float g_v[SEQ * NB * CH];
__device__ float g_attn[SEQ * NB * CH];
__device__ float g_qk[NE * NB * NH];
__device__ float g_pmax[QK_BLOCKS];
__device__ float g_max;

__device__ __forceinline__ uint32_t f2tf32(float x) {
    uint32_t r;
    asm("cvt.rna.tf32.f32 %0, %1;" : "=r"(r) : "f"(x));
    return r;
}

// ============================================================
// TF32 tensor-core GEMM with bias:
//   out[m,n] = sum_k A[m,k] * W[n,k] + bias[n]
// A: [M,K] row-major, W: [N,K] row-major (torch Linear weight)
// 128x128x16 tile, 256 threads (8 warps, 4x2), warp tile 32x64,
// mma.sync.m16n8k8.tf32. Shared stride 20 -> conflict-free frag LDS.
// ============================================================
__global__ __launch_bounds__(256) void tf32_gemm_bias_kernel(
    const float* __restrict__ A, const float* __restrict__ W,
    const float* __restrict__ bias, float* __restrict__ out,
    int M, int N, int K)
{
    constexpr int BM = 128, BN = 128, BK = 16, ST = 20;
    __shared__ uint32_t As[BM * ST];
    __shared__ uint32_t Bs[BN * ST];

    const int bm = blockIdx.y * BM;
    const int bn = blockIdx.x * BN;
    const int t    = threadIdx.x;
    const int lane = t & 31;
    const int warp = t >> 5;
    const int gid  = lane >> 2;   // 0..7
    const int tig  = lane & 3;    // 0..3
    const int wm = (warp >> 1) * 32;  // warp m offset (4 warps in m)
    const int wn = (warp & 1) * 64;   // warp n offset (2 warps in n)

    // global->shared load mapping: thread covers (row = t>>2 [+64], k-cols (t&3)*4..+3)
    const int lrow = t >> 2;          // 0..63
    const int lc4  = (t & 3) * 4;     // 0,4,8,12

    float c[2][8][4];
    #pragma unroll
    for (int mi = 0; mi < 2; mi++)
        #pragma unroll
        for (int ni = 0; ni < 8; ni++)
            #pragma unroll
            for (int r = 0; r < 4; r++) c[mi][ni][r] = 0.0f;

    for (int k0 = 0; k0 < K; k0 += BK) {
        #pragma unroll
        for (int r = 0; r < 2; r++) {
            const int row = lrow + r * 64;
            float4 av = *(const float4*)(A + (size_t)(bm + row) * K + k0 + lc4);
            float4 wv = *(const float4*)(W + (size_t)(bn + row) * K + k0 + lc4);
            uint32_t* as = &As[row * ST + lc4];
            as[0] = f2tf32(av.x); as[1] = f2tf32(av.y);
            as[2] = f2tf32(av.z); as[3] = f2tf32(av.w);
            uint32_t* bs = &Bs[row * ST + lc4];
            bs[0] = f2tf32(wv.x); bs[1] = f2tf32(wv.y);
            bs[2] = f2tf32(wv.z); bs[3] = f2tf32(wv.w);
        }
        __syncthreads();

        #pragma unroll
        for (int ks = 0; ks < BK; ks += 8) {
            uint32_t a[2][4];
            #pragma unroll
            for (int mi = 0; mi < 2; mi++) {
                const int rb = wm + mi * 16;
                a[mi][0] = As[(rb + gid    ) * ST + ks + tig    ];
                a[mi][1] = As[(rb + gid + 8) * ST + ks + tig    ];
                a[mi][2] = As[(rb + gid    ) * ST + ks + tig + 4];
                a[mi][3] = As[(rb + gid + 8) * ST + ks + tig + 4];
            }
            #pragma unroll
            for (int ni = 0; ni < 8; ni++) {
                const int nr = wn + ni * 8 + gid;
                uint32_t b0 = Bs[nr * ST + ks + tig    ];
                uint32_t b1 = Bs[nr * ST + ks + tig + 4];
                #pragma unroll
                for (int mi = 0; mi < 2; mi++) {
                    asm volatile(
                        "mma.sync.aligned.m16n8k8.row.col.f32.tf32.tf32.f32 "
                        "{%0,%1,%2,%3}, {%4,%5,%6,%7}, {%8,%9}, {%0,%1,%2,%3};"
                        : "+f"(c[mi][ni][0]), "+f"(c[mi][ni][1]),
                          "+f"(c[mi][ni][2]), "+f"(c[mi][ni][3])
                        : "r"(a[mi][0]), "r"(a[mi][1]), "r"(a[mi][2]), "r"(a[mi][3]),
                          "r"(b0), "r"(b1));
                }
            }
        }
        __syncthreads();
    }

    // epilogue: c0/c1 = (row gid, cols tig*2, tig*2+1); c2/c3 = row gid+8
    #pragma unroll
    for (int mi = 0; mi < 2; mi++) {
        const int row = bm + wm + mi * 16 + gid;
        #pragma unroll
        for (int ni = 0; ni < 8; ni++) {
            const int col = bn + wn + ni * 8 + tig * 2;
            const float2 bv = *(const float2*)(bias + col);
            *(float2*)(out + (size_t)row * N + col) =
                make_float2(c[mi][ni][0] + bv.x, c[mi][ni][1] + bv.y);
            *(float2*)(out + (size_t)(row + 8) * N + col) =
                make_float2(c[mi][ni][2] + bv.x, c[mi][ni][3] + bv.y);
        }
    }
}

// ============================================================
// Per-edge scaled dot products + per-block max.
// One WARP per (e, b): lanes stride the 4KB channel row with
// interleaved float4s (coalesced 512B/wavefront). Element index
// i = j*128 + lane*4 -> head = 2j + (lane>=16); segmented
// shuffle-reduce within each 16-lane half gives 2 heads per j.
// q_id = repeat(arange(S), EPQ) -> qs = e >> 5 (validated R0).
// ============================================================
__global__ __launch_bounds__(256) void edge_qk_kernel(
    const float* __restrict__ q, const float* __restrict__ k,
    const int* __restrict__ k_id,
    float* __restrict__ qk, float* __restrict__ pmax)
{
    const int t    = threadIdx.x;
    const int lane = t & 31;
    const int w    = blockIdx.x * 8 + (t >> 5);
    const int e = w >> 1;
    const int b = w & 1;
    const int qs = e >> 5;
    const int ks = k_id[e];

    const float4* qp = (const float4*)(q + (size_t)(qs * NB + b) * CH);
    const float4* kp = (const float4*)(k + (size_t)(ks * NB + b) * CH);

    float mloc = -3.4e38f;
    float val[8];
    #pragma unroll
    for (int j = 0; j < 8; j++) {
        float4 a = qp[j * 32 + lane];
        float4 c = kp[j * 32 + lane];
        float p = a.x * c.x + a.y * c.y + a.z * c.z + a.w * c.w;
        p += __shfl_xor_sync(0xffffffffu, p, 1);
        p += __shfl_xor_sync(0xffffffffu, p, 2);
        p += __shfl_xor_sync(0xffffffffu, p, 4);
        p += __shfl_xor_sync(0xffffffffu, p, 8);   // halves stay separate
        p *= 0.125f;                               // 1/sqrt(64)
        val[j] = p;
        mloc = fmaxf(mloc, p);
    }

    float* dst = qk + (size_t)(e * NB + b) * NH;
    if (lane == 0) {
        #pragma unroll
        for (int j = 0; j < 8; j++) dst[2 * j] = val[j];       // even heads
    } else if (lane == 16) {
        #pragma unroll
        for (int j = 0; j < 8; j++) dst[2 * j + 1] = val[j];   // odd heads
    }

    __shared__ float red[256];
    red[t] = mloc;
    __syncthreads();
    #pragma unroll
    for (int off = 128; off > 0; off >>= 1) {
        if (t < off) red[t] = fmaxf(red[t], red[t + off]);
        __syncthreads();
    }
    if (t == 0) pmax[blockIdx.x] = red[0];
}

// ============================================================
// final max over partials (single block, deterministic)
// ============================================================
__global__ __launch_bounds__(256) void reduce_max_kernel(
    const float* __restrict__ pmax, int n, float* __restrict__ gmax)
{
    __shared__ float red[256];
    float m = -3.4e38f;
    for (int i = threadIdx.x; i < n; i += 256) m = fmaxf(m, pmax[i]);
    red[threadIdx.x] = m;
    __syncthreads();
    #pragma unroll
    for (int off = 128; off > 0; off >>= 1) {
        if (threadIdx.x < off)
            red[threadIdx.x] = fmaxf(red[threadIdx.x], red[threadIdx.x + off]);
        __syncthreads();
    }
    if (threadIdx.x == 0) *gmax = red[0];
}

// ============================================================
// Segment softmax + weighted value aggregation.
// Contiguous 32-edge segments per query -> no atomics.
// One warp per (s, b, h); lane covers 2 channels (coalesced 256B rows).
// ============================================================
__global__ __launch_bounds__(256) void aggregate_kernel(
    const float* __restrict__ qk, const float* __restrict__ v,
    const int* __restrict__ k_id, const float* __restrict__ gmax,
    float* __restrict__ attn)
{
    const int gtid = blockIdx.x * 256 + threadIdx.x;
    const int wid  = gtid >> 5;
    const int lane = gtid & 31;
    const int h = wid & (NH - 1);
    const int b = (wid >> 4) & (NB - 1);
    const int s = wid >> 5;

    const float mx = *gmax;
    float nx = 0.0f, ny = 0.0f, d = 0.0f;
    const int ebase = s * EPQ;

    #pragma unroll 4
    for (int j = 0; j < EPQ; j++) {
        const int e = ebase + j;
        const float w = expf(qk[(e * NB + b) * NH + h] - mx);
        d += w;
        const int ks = k_id[e];
        const float2 vv = *(const float2*)(
            v + (size_t)(((ks * NB + b) * NH + h)) * CC + lane * 2);
        nx += w * vv.x;
        ny += w * vv.y;
    }
    const float inv = 1.0f / d;
    *(float2*)(attn + (size_t)(((s * NB + b) * NH + h)) * CC + lane * 2)
        = make_float2(nx * inv, ny * inv);
}

// ============================================================
// host launcher (graph-capturable: kernel launches only)
// ============================================================
extern "C" void kernel_launch(void* const* d_in, const int* in_sizes, int n_in,
                              void* d_out, int out_size)
{
    const float* x   = (const float*)d_in[0];
    const int*  k_id = (const int*)d_in[2];
    const float* Wq  = (const float*)d_in[3];
    const float* bq  = (const float*)d_in[4];
    const float* Wk  = (const float*)d_in[5];
    const float* bk  = (const float*)d_in[6];
    const float* Wv  = (const float*)d_in[7];
    const float* bv  = (const float*)d_in[8];
    const float* Wx  = (const float*)d_in[9];
    const float* bx  = (const float*)d_in[10];
    float* out = (float*)d_out;

    float *q, *k, *v, *attn, *qkbuf, *pmax, *gmax;
    cudaGetSymbolAddress((void**)&q,     g_q);
    cudaGetSymbolAddress((void**)&k,     g_k);
    cudaGetSymbolAddress((void**)&v,     g_v);
    cudaGetSymbolAddress((void**)&attn,  g_attn);
    cudaGetSymbolAddress((void**)&qkbuf, g_qk);
    cudaGetSymbolAddress((void**)&pmax,  g_pmax);
    cudaGetSymbolAddress((void**)&gmax,  g_max);

    const dim3 gemm_grid(CH / 128, MROWS / 128);   // (8, 32)

    // q/k/v projections (tensor cores, tf32)
    tf32_gemm_bias_kernel<<<gemm_grid, 256>>>(x, Wq, bq, q, MROWS, CH, CH);
    tf32_gemm_bias_kernel<<<gemm_grid, 256>>>(x, Wk, bk, k, MROWS, CH, CH);
    tf32_gemm_bias_kernel<<<gemm_grid, 256>>>(x, Wv, bv, v, MROWS, CH, CH);

    // per-edge dots + global max
    edge_qk_kernel<<<QK_BLOCKS, 256>>>(q, k, k_id, qkbuf, pmax);
    reduce_max_kernel<<<1, 256>>>(pmax, QK_BLOCKS, gmax);

    // segment softmax + V aggregation
    aggregate_kernel<<<AGG_BLOCKS, 256>>>(qkbuf, v, k_id, gmax, attn);

    // output projection
    tf32_gemm_bias_kernel<<<gemm_grid, 256>>>(attn, Wx, bx, out, MROWS, CH, CH);
}

// round 4
// speedup vs baseline: 3.1354x; 1.1917x over previous
#include <cuda_runtime.h>
#include <cuda_bf16.h>
#include <cstdint>

// Problem constants
constexpr int SEQ = 2048;
constexpr int NB  = 2;      // batch
constexpr int CH  = 1024;   // channels
constexpr int NH  = 16;     // heads
constexpr int EPQ = 32;     // edges per query
constexpr int NE  = SEQ * EPQ;          // 65536 edges
constexpr int MROWS = SEQ * NB;         // 4096 GEMM rows
constexpr int QKV_N = 3 * CH;           // 3072 fused projection cols
constexpr int QK_BLOCKS = SEQ * NB;     // 4096 (block per (query, b))

// -------- device scratch (no allocations allowed) --------
__device__ float g_qkv[MROWS * QKV_N];   // q | k | v interleaved per row
__device__ float g_attn[MROWS * CH];
__device__ float g_qk[NE * NB * NH];
__device__ float g_pmax[QK_BLOCKS];
__device__ float g_max;

__device__ __forceinline__ uint32_t f2tf32(float x) {
    uint32_t r;
    asm("cvt.rna.tf32.f32 %0, %1;" : "=r"(r) : "f"(x));
    return r;
}

__device__ __forceinline__ void cp_async16(void* sptr, const void* gptr) {
    uint32_t sa = (uint32_t)__cvta_generic_to_shared(sptr);
    asm volatile("cp.async.cg.shared.global [%0], [%1], 16;" :: "r"(sa), "l"(gptr));
}

// ============================================================
// TF32 tensor-core GEMM with bias, double-buffered cp.async.
//   out[m,n] = sum_k A[m,k] * Wsel[nmod,k] + bsel[nmod]
// Weight/bias selected per 1024-column segment (fused qkv).
// 128x128x16 tile, 256 thr (8 warps 4x2, warp tile 32x64),
// mma.sync.m16n8k8.tf32, smem row stride 20 floats (pad via
// per-16B-chunk cp.async addresses) -> conflict-free frag LDS.
// ============================================================
__global__ __launch_bounds__(256) void tf32_gemm_bias_kernel(
    const float* __restrict__ A,
    const float* __restrict__ W0, const float* __restrict__ W1,
    const float* __restrict__ W2,
    const float* __restrict__ b0, const float* __restrict__ b1,
    const float* __restrict__ b2,
    float* __restrict__ out, int N, int K)
{
    constexpr int ST = 20;
    __shared__ float As[2][128 * ST];
    __shared__ float Bs[2][128 * ST];

    const int bm = blockIdx.y * 128;
    const int bn = blockIdx.x * 128;
    const int sel = bn >> 10;
    const float* W = sel == 0 ? W0 : (sel == 1 ? W1 : W2);
    const float* bias = sel == 0 ? b0 : (sel == 1 ? b1 : b2);
    const int wbase = bn & 1023;

    const int t    = threadIdx.x;
    const int lane = t & 31;
    const int warp = t >> 5;
    const int gid  = lane >> 2;
    const int tig  = lane & 3;
    const int wm = (warp >> 1) * 32;
    const int wn = (warp & 1) * 64;

    float c[2][8][4];
    #pragma unroll
    for (int mi = 0; mi < 2; mi++)
        #pragma unroll
        for (int ni = 0; ni < 8; ni++)
            #pragma unroll
            for (int r = 0; r < 4; r++) c[mi][ni][r] = 0.0f;

    // stage copy: 512 16B chunks per tile, 2 per thread per tile
    auto issue = [&](int k0, int st) {
        #pragma unroll
        for (int i = 0; i < 2; i++) {
            const int ch = t + i * 256;
            const int row = ch >> 2, cc4 = (ch & 3) * 4;
            cp_async16(&As[st][row * ST + cc4],
                       A + (size_t)(bm + row) * K + k0 + cc4);
            cp_async16(&Bs[st][row * ST + cc4],
                       W + (size_t)(wbase + row) * K + k0 + cc4);
        }
        asm volatile("cp.async.commit_group;");
    };

    const int NSTEP = K / 16;
    issue(0, 0);

    for (int s = 0; s < NSTEP; s++) {
        const int buf = s & 1;
        if (s + 1 < NSTEP) {
            issue((s + 1) * 16, buf ^ 1);
            asm volatile("cp.async.wait_group 1;");
        } else {
            asm volatile("cp.async.wait_group 0;");
        }
        __syncthreads();

        #pragma unroll
        for (int ks = 0; ks < 16; ks += 8) {
            uint32_t a[2][4];
            #pragma unroll
            for (int mi = 0; mi < 2; mi++) {
                const int rb = wm + mi * 16;
                a[mi][0] = f2tf32(As[buf][(rb + gid    ) * ST + ks + tig    ]);
                a[mi][1] = f2tf32(As[buf][(rb + gid + 8) * ST + ks + tig    ]);
                a[mi][2] = f2tf32(As[buf][(rb + gid    ) * ST + ks + tig + 4]);
                a[mi][3] = f2tf32(As[buf][(rb + gid + 8) * ST + ks + tig + 4]);
            }
            #pragma unroll
            for (int ni = 0; ni < 8; ni++) {
                const int nr = wn + ni * 8 + gid;
                uint32_t bq0 = f2tf32(Bs[buf][nr * ST + ks + tig    ]);
                uint32_t bq1 = f2tf32(Bs[buf][nr * ST + ks + tig + 4]);
                #pragma unroll
                for (int mi = 0; mi < 2; mi++) {
                    asm volatile(
                        "mma.sync.aligned.m16n8k8.row.col.f32.tf32.tf32.f32 "
                        "{%0,%1,%2,%3}, {%4,%5,%6,%7}, {%8,%9}, {%0,%1,%2,%3};"
                        : "+f"(c[mi][ni][0]), "+f"(c[mi][ni][1]),
                          "+f"(c[mi][ni][2]), "+f"(c[mi][ni][3])
                        : "r"(a[mi][0]), "r"(a[mi][1]), "r"(a[mi][2]), "r"(a[mi][3]),
                          "r"(bq0), "r"(bq1));
                }
            }
        }
        __syncthreads();
    }

    #pragma unroll
    for (int mi = 0; mi < 2; mi++) {
        const int row = bm + wm + mi * 16 + gid;
        #pragma unroll
        for (int ni = 0; ni < 8; ni++) {
            const int col = bn + wn + ni * 8 + tig * 2;
            const float2 bv = *(const float2*)(bias + (wbase + wn + ni * 8 + tig * 2));
            *(float2*)(out + (size_t)row * N + col) =
                make_float2(c[mi][ni][0] + bv.x, c[mi][ni][1] + bv.y);
            *(float2*)(out + (size_t)(row + 8) * N + col) =
                make_float2(c[mi][ni][2] + bv.x, c[mi][ni][3] + bv.y);
        }
    }
}

// ============================================================
// Per-edge scaled dot products + per-block max.
// Block per (query qs, b): q row (4KB) staged in smem ONCE,
// 8 warps x 4 edges gather k rows. Lane reads float4 at element
// j*128 + lane*4 -> head = 2j + (lane>=16); xor-shuffle over
// {1,2,4,8} reduces each 16-lane half -> 2 heads per j.
// q_id = repeat(arange(S), EPQ) -> query = e >> 5.
// ============================================================
__global__ __launch_bounds__(256) void edge_qk_kernel(
    const float* __restrict__ qkv, const int* __restrict__ k_id,
    float* __restrict__ qk, float* __restrict__ pmax)
{
    __shared__ float4 qs4[CH / 4];
    __shared__ int ksm[EPQ];
    __shared__ float red[8];

    const int qs = blockIdx.x >> 1;
    const int b  = blockIdx.x & 1;
    const int t    = threadIdx.x;
    const int lane = t & 31;
    const int warp = t >> 5;
    const int ebase = qs * EPQ;

    // stage q row + edge ids
    qs4[t] = *((const float4*)(qkv + (size_t)(qs * NB + b) * QKV_N) + t);
    if (t < EPQ) ksm[t] = k_id[ebase + t];
    __syncthreads();

    float mloc = -3.4e38f;
    #pragma unroll
    for (int i = 0; i < 4; i++) {
        const int e = warp * 4 + i;                 // local edge 0..31
        const float4* kp = (const float4*)(
            qkv + (size_t)(ksm[e] * NB + b) * QKV_N + CH);
        float val[8];
        #pragma unroll
        for (int j = 0; j < 8; j++) {
            float4 a = qs4[j * 32 + lane];
            float4 c = kp[j * 32 + lane];
            float p = a.x * c.x + a.y * c.y + a.z * c.z + a.w * c.w;
            p += __shfl_xor_sync(0xffffffffu, p, 1);
            p += __shfl_xor_sync(0xffffffffu, p, 2);
            p += __shfl_xor_sync(0xffffffffu, p, 4);
            p += __shfl_xor_sync(0xffffffffu, p, 8);   // halves stay separate
            p *= 0.125f;                               // 1/sqrt(64)
            val[j] = p;
            mloc = fmaxf(mloc, p);
        }
        float* dst = qk + (size_t)((ebase + e) * NB + b) * NH;
        if (lane == 0) {
            #pragma unroll
            for (int j = 0; j < 8; j++) dst[2 * j] = val[j];
        } else if (lane == 16) {
            #pragma unroll
            for (int j = 0; j < 8; j++) dst[2 * j + 1] = val[j];
        }
    }

    // block max (only lanes 0/16 hold real head values, but max over
    // partial sums >= ... must reduce only finished values: mloc on all
    // lanes tracks fully-reduced p (post-shuffle), identical in each half)
    mloc = fmaxf(mloc, __shfl_xor_sync(0xffffffffu, mloc, 16));
    if (lane == 0) red[warp] = mloc;
    __syncthreads();
    if (t == 0) {
        float m = red[0];
        #pragma unroll
        for (int w = 1; w < 8; w++) m = fmaxf(m, red[w]);
        pmax[blockIdx.x] = m;
    }
}

// ============================================================
// final max over partials (single block, deterministic)
// ============================================================
__global__ __launch_bounds__(256) void reduce_max_kernel(
    const float* __restrict__ pmax, int n, float* __restrict__ gmax)
{
    __shared__ float red[256];
    float m = -3.4e38f;
    for (int i = threadIdx.x; i < n; i += 256) m = fmaxf(m, pmax[i]);
    red[threadIdx.x] = m;
    __syncthreads();
    #pragma unroll
    for (int off = 128; off > 0; off >>= 1) {
        if (threadIdx.x < off)
            red[threadIdx.x] = fmaxf(red[threadIdx.x], red[threadIdx.x + off]);
        __syncthreads();
    }
    if (threadIdx.x == 0) *gmax = red[0];
}

// ============================================================
// Segment softmax + weighted value aggregation.
// Block per (s, b). Stage 1: 512 exp weights + per-head denom in
// smem (computed ONCE). Stage 2: 256 threads sweep 32 v rows with
// full-row coalesced float4 loads; w broadcast from smem.
// ============================================================
__global__ __launch_bounds__(256) void aggregate_kernel(
    const float* __restrict__ qk, const float* __restrict__ qkv,
    const int* __restrict__ k_id, const float* __restrict__ gmax,
    float* __restrict__ attn)
{
    __shared__ float sw[EPQ * NH];     // w[e][h]
    __shared__ float sinvd[NH];
    __shared__ int ksm[EPQ];

    const int s = blockIdx.x >> 1;
    const int b = blockIdx.x & 1;
    const int t = threadIdx.x;
    const int ebase = s * EPQ;
    const float mx = *gmax;

    if (t < EPQ) ksm[t] = k_id[ebase + t];
    #pragma unroll
    for (int i = 0; i < 2; i++) {
        const int idx = t + i * 256;          // < 512
        const int e = idx >> 4, h = idx & 15;
        sw[idx] = expf(qk[(size_t)((ebase + e) * NB + b) * NH + h] - mx);
    }
    __syncthreads();
    if (t < NH) {
        float d = 0.0f;
        #pragma unroll
        for (int e = 0; e < EPQ; e++) d += sw[e * NH + t];
        sinvd[t] = 1.0f / d;
    }
    __syncthreads();

    const int h = t >> 4;                      // head of my 4 channels
    float4 acc = make_float4(0.f, 0.f, 0.f, 0.f);
    #pragma unroll 4
    for (int e = 0; e < EPQ; e++) {
        const float w = sw[e * NH + h];
        const float4 vv = *((const float4*)(
            qkv + (size_t)(ksm[e] * NB + b) * QKV_N + 2 * CH) + t);
        acc.x += w * vv.x; acc.y += w * vv.y;
        acc.z += w * vv.z; acc.w += w * vv.w;
    }
    const float inv = sinvd[h];
    acc.x *= inv; acc.y *= inv; acc.z *= inv; acc.w *= inv;
    *((float4*)(attn + (size_t)(s * NB + b) * CH) + t) = acc;
}

// ============================================================
// host launcher (graph-capturable: kernel launches only)
// ============================================================
extern "C" void kernel_launch(void* const* d_in, const int* in_sizes, int n_in,
                              void* d_out, int out_size)
{
    const float* x   = (const float*)d_in[0];
    const int*  k_id = (const int*)d_in[2];
    const float* Wq  = (const float*)d_in[3];
    const float* bq  = (const float*)d_in[4];
    const float* Wk  = (const float*)d_in[5];
    const float* bk  = (const float*)d_in[6];
    const float* Wv  = (const float*)d_in[7];
    const float* bv  = (const float*)d_in[8];
    const float* Wx  = (const float*)d_in[9];
    const float* bx  = (const float*)d_in[10];
    float* out = (float*)d_out;

    float *qkv, *attn, *qkbuf, *pmax, *gmax;
    cudaGetSymbolAddress((void**)&qkv,   g_qkv);
    cudaGetSymbolAddress((void**)&attn,  g_attn);
    cudaGetSymbolAddress((void**)&qkbuf, g_qk);
    cudaGetSymbolAddress((void**)&pmax,  g_pmax);
    cudaGetSymbolAddress((void**)&gmax,  g_max);

    // fused q/k/v projection: one GEMM, N=3072
    tf32_gemm_bias_kernel<<<dim3(QKV_N / 128, MROWS / 128), 256>>>(
        x, Wq, Wk, Wv, bq, bk, bv, qkv, QKV_N, CH);

    // per-edge dots + global max
    edge_qk_kernel<<<QK_BLOCKS, 256>>>(qkv, k_id, qkbuf, pmax);
    reduce_max_kernel<<<1, 256>>>(pmax, QK_BLOCKS, gmax);

    // segment softmax + V aggregation
    aggregate_kernel<<<QK_BLOCKS, 256>>>(qkbuf, qkv, k_id, gmax, attn);

    // output projection
    tf32_gemm_bias_kernel<<<dim3(CH / 128, MROWS / 128), 256>>>(
        attn, Wx, Wx, Wx, bx, bx, bx, out, CH, CH);
}

// round 5
// speedup vs baseline: 3.3981x; 1.0838x over previous
#include <cuda_runtime.h>
#include <cuda_bf16.h>
#include <cstdint>

// Problem constants
constexpr int SEQ = 2048;
constexpr int NB  = 2;      // batch
constexpr int CH  = 1024;   // channels
constexpr int NH  = 16;     // heads
constexpr int EPQ = 32;     // edges per query
constexpr int NE  = SEQ * EPQ;          // 65536 edges
constexpr int MROWS = SEQ * NB;         // 4096 GEMM rows
constexpr int QKV_N = 3 * CH;           // 3072 fused projection cols
constexpr int QK_BLOCKS = SEQ * NB;     // 4096 (block per (query, b))

// -------- device scratch (no allocations allowed) --------
__device__ float g_qkv[MROWS * QKV_N];   // q | k | v per row
__device__ float g_attn[MROWS * CH];
__device__ float g_qk[NE * NB * NH];
__device__ float g_pmax[QK_BLOCKS];
__device__ float g_max;
__device__ float g_xc[MROWS * CH];       // tf32-rounded x
__device__ float g_wc[4 * CH * CH];      // tf32-rounded Wq|Wk|Wv|Wx

__device__ __forceinline__ float f2tf32f(float x) {
    uint32_t r;
    asm("cvt.rna.tf32.f32 %0, %1;" : "=r"(r) : "f"(x));
    return __uint_as_float(r);
}

__device__ __forceinline__ void cp_async16(void* sptr, const void* gptr) {
    uint32_t sa = (uint32_t)__cvta_generic_to_shared(sptr);
    asm volatile("cp.async.cg.shared.global [%0], [%1], 16;" :: "r"(sa), "l"(gptr));
}

__device__ __forceinline__ void ldsm_x4(uint32_t addr, uint32_t& r0, uint32_t& r1,
                                        uint32_t& r2, uint32_t& r3) {
    asm volatile("ldmatrix.sync.aligned.m8n8.x4.shared.b16 {%0,%1,%2,%3}, [%4];"
                 : "=r"(r0), "=r"(r1), "=r"(r2), "=r"(r3) : "r"(addr));
}

// ============================================================
// elementwise tf32 rounding (pre-pass; numerics identical to
// converting at fragment-load time)
// ============================================================
__global__ __launch_bounds__(256) void cvt_tf32_kernel(
    const float4* __restrict__ src, float4* __restrict__ dst, int n4)
{
    const int i = blockIdx.x * 256 + threadIdx.x;
    if (i < n4) {
        float4 v = src[i];
        dst[i] = make_float4(f2tf32f(v.x), f2tf32f(v.y), f2tf32f(v.z), f2tf32f(v.w));
    }
}

// ============================================================
// TF32 tensor-core GEMM with bias, double-buffered cp.async.
// Inputs A/W are PRE-ROUNDED to tf32 -> no cvt in the loop; all
// fragment loads via ldmatrix.x4 (b16 pair layout == tf32 frag).
//   out[m,n] = sum_k A[m,k] * Wsel[nmod,k] + bsel[nmod]
// 128x128x16 tile, 256 thr (8 warps 4x2, warp tile 32x64),
// smem row stride 20 floats -> ldmatrix conflict-free.
// ============================================================
__global__ __launch_bounds__(256) void tf32_gemm_bias_kernel(
    const float* __restrict__ A,
    const float* __restrict__ W0, const float* __restrict__ W1,
    const float* __restrict__ W2,
    const float* __restrict__ b0, const float* __restrict__ b1,
    const float* __restrict__ b2,
    float* __restrict__ out, int N, int K)
{
    constexpr int ST = 20;
    __shared__ float As[2][128 * ST];
    __shared__ float Bs[2][128 * ST];

    const int bm = blockIdx.y * 128;
    const int bn = blockIdx.x * 128;
    const int sel = bn >> 10;
    const float* W = sel == 0 ? W0 : (sel == 1 ? W1 : W2);
    const float* bias = sel == 0 ? b0 : (sel == 1 ? b1 : b2);
    const int wbase = bn & 1023;

    const int t    = threadIdx.x;
    const int lane = t & 31;
    const int warp = t >> 5;
    const int gid  = lane >> 2;
    const int tig  = lane & 3;
    const int wm = (warp >> 1) * 32;
    const int wn = (warp & 1) * 64;

    // ldmatrix per-thread address offsets (in floats)
    const int g      = lane >> 3;   // quad group 0..3
    const int row_in = lane & 7;
    const int aoff = (wm + (g & 1) * 8 + row_in) * ST + (g >> 1) * 4;
    const int boff = (wn + (g >> 1) * 8 + row_in) * ST + (g & 1) * 4;

    const uint32_t sAs = (uint32_t)__cvta_generic_to_shared(&As[0][0]);
    const uint32_t sBs = (uint32_t)__cvta_generic_to_shared(&Bs[0][0]);
    constexpr uint32_t BUFB = 128 * ST * 4;   // bytes per stage

    float c[2][8][4];
    #pragma unroll
    for (int mi = 0; mi < 2; mi++)
        #pragma unroll
        for (int ni = 0; ni < 8; ni++)
            #pragma unroll
            for (int r = 0; r < 4; r++) c[mi][ni][r] = 0.0f;

    auto issue = [&](int k0, int st) {
        #pragma unroll
        for (int i = 0; i < 2; i++) {
            const int ch = t + i * 256;
            const int row = ch >> 2, cc4 = (ch & 3) * 4;
            cp_async16(&As[st][row * ST + cc4],
                       A + (size_t)(bm + row) * K + k0 + cc4);
            cp_async16(&Bs[st][row * ST + cc4],
                       W + (size_t)(wbase + row) * K + k0 + cc4);
        }
        asm volatile("cp.async.commit_group;");
    };

    const int NSTEP = K / 16;
    issue(0, 0);

    for (int s = 0; s < NSTEP; s++) {
        const int buf = s & 1;
        if (s + 1 < NSTEP) {
            issue((s + 1) * 16, buf ^ 1);
            asm volatile("cp.async.wait_group 1;");
        } else {
            asm volatile("cp.async.wait_group 0;");
        }
        __syncthreads();

        const uint32_t aBase = sAs + buf * BUFB + aoff * 4;
        const uint32_t bBase = sBs + buf * BUFB + boff * 4;

        #pragma unroll
        for (int ks = 0; ks < 16; ks += 8) {
            uint32_t a[2][4];
            #pragma unroll
            for (int mi = 0; mi < 2; mi++)
                ldsm_x4(aBase + (mi * 16 * ST + ks) * 4,
                        a[mi][0], a[mi][1], a[mi][2], a[mi][3]);

            uint32_t b[8][2];
            #pragma unroll
            for (int ni2 = 0; ni2 < 4; ni2++)
                ldsm_x4(bBase + (ni2 * 16 * ST + ks) * 4,
                        b[2 * ni2][0], b[2 * ni2][1],
                        b[2 * ni2 + 1][0], b[2 * ni2 + 1][1]);

            #pragma unroll
            for (int ni = 0; ni < 8; ni++)
                #pragma unroll
                for (int mi = 0; mi < 2; mi++) {
                    asm volatile(
                        "mma.sync.aligned.m16n8k8.row.col.f32.tf32.tf32.f32 "
                        "{%0,%1,%2,%3}, {%4,%5,%6,%7}, {%8,%9}, {%0,%1,%2,%3};"
                        : "+f"(c[mi][ni][0]), "+f"(c[mi][ni][1]),
                          "+f"(c[mi][ni][2]), "+f"(c[mi][ni][3])
                        : "r"(a[mi][0]), "r"(a[mi][1]), "r"(a[mi][2]), "r"(a[mi][3]),
                          "r"(b[ni][0]), "r"(b[ni][1]));
                }
        }
        __syncthreads();
    }

    #pragma unroll
    for (int mi = 0; mi < 2; mi++) {
        const int row = bm + wm + mi * 16 + gid;
        #pragma unroll
        for (int ni = 0; ni < 8; ni++) {
            const int col = bn + wn + ni * 8 + tig * 2;
            const float2 bv = *(const float2*)(bias + (wbase + wn + ni * 8 + tig * 2));
            *(float2*)(out + (size_t)row * N + col) =
                make_float2(c[mi][ni][0] + bv.x, c[mi][ni][1] + bv.y);
            *(float2*)(out + (size_t)(row + 8) * N + col) =
                make_float2(c[mi][ni][2] + bv.x, c[mi][ni][3] + bv.y);
        }
    }
}

// ============================================================
// Per-edge scaled dot products + per-block max.
// Block per (query qs, b): q row staged in smem once, 8 warps x
// 4 edges gather k rows. head = 2j + (lane>=16); xor-shuffle
// {1,2,4,8} reduces each 16-lane half.
// q_id = repeat(arange(S), EPQ) -> query = e >> 5.
// ============================================================
__global__ __launch_bounds__(256) void edge_qk_kernel(
    const float* __restrict__ qkv, const int* __restrict__ k_id,
    float* __restrict__ qk, float* __restrict__ pmax)
{
    __shared__ float4 qs4[CH / 4];
    __shared__ int ksm[EPQ];
    __shared__ float red[8];

    const int qs = blockIdx.x >> 1;
    const int b  = blockIdx.x & 1;
    const int t    = threadIdx.x;
    const int lane = t & 31;
    const int warp = t >> 5;
    const int ebase = qs * EPQ;

    qs4[t] = *((const float4*)(qkv + (size_t)(qs * NB + b) * QKV_N) + t);
    if (t < EPQ) ksm[t] = k_id[ebase + t];
    __syncthreads();

    float mloc = -3.4e38f;
    #pragma unroll
    for (int i = 0; i < 4; i++) {
        const int e = warp * 4 + i;
        const float4* kp = (const float4*)(
            qkv + (size_t)(ksm[e] * NB + b) * QKV_N + CH);
        float val[8];
        #pragma unroll
        for (int j = 0; j < 8; j++) {
            float4 a = qs4[j * 32 + lane];
            float4 cc = kp[j * 32 + lane];
            float p = a.x * cc.x + a.y * cc.y + a.z * cc.z + a.w * cc.w;
            p += __shfl_xor_sync(0xffffffffu, p, 1);
            p += __shfl_xor_sync(0xffffffffu, p, 2);
            p += __shfl_xor_sync(0xffffffffu, p, 4);
            p += __shfl_xor_sync(0xffffffffu, p, 8);
            p *= 0.125f;
            val[j] = p;
            mloc = fmaxf(mloc, p);
        }
        float* dst = qk + (size_t)((ebase + e) * NB + b) * NH;
        if (lane == 0) {
            #pragma unroll
            for (int j = 0; j < 8; j++) dst[2 * j] = val[j];
        } else if (lane == 16) {
            #pragma unroll
            for (int j = 0; j < 8; j++) dst[2 * j + 1] = val[j];
        }
    }

    mloc = fmaxf(mloc, __shfl_xor_sync(0xffffffffu, mloc, 16));
    if (lane == 0) red[warp] = mloc;
    __syncthreads();
    if (t == 0) {
        float m = red[0];
        #pragma unroll
        for (int w = 1; w < 8; w++) m = fmaxf(m, red[w]);
        pmax[blockIdx.x] = m;
    }
}

// ============================================================
// final max over partials (single block, deterministic)
// ============================================================
__global__ __launch_bounds__(256) void reduce_max_kernel(
    const float* __restrict__ pmax, int n, float* __restrict__ gmax)
{
    __shared__ float red[256];
    float m = -3.4e38f;
    for (int i = threadIdx.x; i < n; i += 256) m = fmaxf(m, pmax[i]);
    red[threadIdx.x] = m;
    __syncthreads();
    #pragma unroll
    for (int off = 128; off > 0; off >>= 1) {
        if (threadIdx.x < off)
            red[threadIdx.x] = fmaxf(red[threadIdx.x], red[threadIdx.x + off]);
        __syncthreads();
    }
    if (threadIdx.x == 0) *gmax = red[0];
}

// ============================================================
// Segment softmax + weighted value aggregation.
// Block per (s, b). Weights computed once in smem; 256 threads
// sweep 32 v rows with coalesced float4 loads. Output rounded to
// tf32 so the out-GEMM needs no cvt (numerics == cvt-at-load).
// ============================================================
__global__ __launch_bounds__(256) void aggregate_kernel(
    const float* __restrict__ qk, const float* __restrict__ qkv,
    const int* __restrict__ k_id, const float* __restrict__ gmax,
    float* __restrict__ attn)
{
    __shared__ float sw[EPQ * NH];
    __shared__ float sinvd[NH];
    __shared__ int ksm[EPQ];

    const int s = blockIdx.x >> 1;
    const int b = blockIdx.x & 1;
    const int t = threadIdx.x;
    const int ebase = s * EPQ;
    const float mx = *gmax;

    if (t < EPQ) ksm[t] = k_id[ebase + t];
    #pragma unroll
    for (int i = 0; i < 2; i++) {
        const int idx = t + i * 256;
        const int e = idx >> 4, h = idx & 15;
        sw[idx] = expf(qk[(size_t)((ebase + e) * NB + b) * NH + h] - mx);
    }
    __syncthreads();
    if (t < NH) {
        float d = 0.0f;
        #pragma unroll
        for (int e = 0; e < EPQ; e++) d += sw[e * NH + t];
        sinvd[t] = 1.0f / d;
    }
    __syncthreads();

    const int h = t >> 4;
    float4 acc = make_float4(0.f, 0.f, 0.f, 0.f);
    #pragma unroll 4
    for (int e = 0; e < EPQ; e++) {
        const float w = sw[e * NH + h];
        const float4 vv = *((const float4*)(
            qkv + (size_t)(ksm[e] * NB + b) * QKV_N + 2 * CH) + t);
        acc.x += w * vv.x; acc.y += w * vv.y;
        acc.z += w * vv.z; acc.w += w * vv.w;
    }
    const float inv = sinvd[h];
    *((float4*)(attn + (size_t)(s * NB + b) * CH) + t) =
        make_float4(f2tf32f(acc.x * inv), f2tf32f(acc.y * inv),
                    f2tf32f(acc.z * inv), f2tf32f(acc.w * inv));
}

// ============================================================
// host launcher (graph-capturable: kernel launches only)
// ============================================================
extern "C" void kernel_launch(void* const* d_in, const int* in_sizes, int n_in,
                              void* d_out, int out_size)
{
    const float* x   = (const float*)d_in[0];
    const int*  k_id = (const int*)d_in[2];
    const float* Wq  = (const float*)d_in[3];
    const float* bq  = (const float*)d_in[4];
    const float* Wk  = (const float*)d_in[5];
    const float* bk  = (const float*)d_in[6];
    const float* Wv  = (const float*)d_in[7];
    const float* bv  = (const float*)d_in[8];
    const float* Wx  = (const float*)d_in[9];
    const float* bx  = (const float*)d_in[10];
    float* out = (float*)d_out;

    float *qkv, *attn, *qkbuf, *pmax, *gmax, *xc, *wc;
    cudaGetSymbolAddress((void**)&qkv,   g_qkv);
    cudaGetSymbolAddress((void**)&attn,  g_attn);
    cudaGetSymbolAddress((void**)&qkbuf, g_qk);
    cudaGetSymbolAddress((void**)&pmax,  g_pmax);
    cudaGetSymbolAddress((void**)&gmax,  g_max);
    cudaGetSymbolAddress((void**)&xc,    g_xc);
    cudaGetSymbolAddress((void**)&wc,    g_wc);

    constexpr int WSZ = CH * CH;            // 1M elements per weight
    constexpr int XN4 = MROWS * CH / 4;     // 1,048,576
    constexpr int WN4 = WSZ / 4;            // 262,144

    // tf32 pre-rounding (bit-identical to cvt at fragment load)
    cvt_tf32_kernel<<<XN4 / 256, 256>>>((const float4*)x,  (float4*)xc, XN4);
    cvt_tf32_kernel<<<WN4 / 256, 256>>>((const float4*)Wq, (float4*)(wc + 0 * WSZ), WN4);
    cvt_tf32_kernel<<<WN4 / 256, 256>>>((const float4*)Wk, (float4*)(wc + 1 * WSZ), WN4);
    cvt_tf32_kernel<<<WN4 / 256, 256>>>((const float4*)Wv, (float4*)(wc + 2 * WSZ), WN4);
    cvt_tf32_kernel<<<WN4 / 256, 256>>>((const float4*)Wx, (float4*)(wc + 3 * WSZ), WN4);

    // fused q/k/v projection: one GEMM, N=3072
    tf32_gemm_bias_kernel<<<dim3(QKV_N / 128, MROWS / 128), 256>>>(
        xc, wc + 0 * WSZ, wc + 1 * WSZ, wc + 2 * WSZ, bq, bk, bv, qkv, QKV_N, CH);

    // per-edge dots + global max
    edge_qk_kernel<<<QK_BLOCKS, 256>>>(qkv, k_id, qkbuf, pmax);
    reduce_max_kernel<<<1, 256>>>(pmax, QK_BLOCKS, gmax);

    // segment softmax + V aggregation (writes tf32-rounded attn)
    aggregate_kernel<<<QK_BLOCKS, 256>>>(qkbuf, qkv, k_id, gmax, attn);

    // output projection
    tf32_gemm_bias_kernel<<<dim3(CH / 128, MROWS / 128), 256>>>(
        attn, wc + 3 * WSZ, wc + 3 * WSZ, wc + 3 * WSZ, bx, bx, bx, out, CH, CH);
}

// round 7
// speedup vs baseline: 4.7728x; 1.4046x over previous
#include <cuda_runtime.h>
#include <cuda_fp16.h>
#include <cstdint>

// Problem constants
constexpr int SEQ = 2048;
constexpr int NB  = 2;      // batch
constexpr int CH  = 1024;   // channels
constexpr int NH  = 16;     // heads
constexpr int EPQ = 32;     // edges per query
constexpr int NE  = SEQ * EPQ;          // 65536 edges
constexpr int MROWS = SEQ * NB;         // 4096 GEMM rows
constexpr int QKV_N = 3 * CH;           // 3072 fused projection cols
constexpr int QK_BLOCKS = SEQ * NB;     // 4096

// -------- device scratch (no allocations allowed) --------
__device__ float  g_qkv[MROWS * QKV_N];   // q | k | v per row (fp32)
__device__ __half g_attn[MROWS * CH];     // attention output (fp16, GEMM input)
__device__ float  g_qk[NE * NB * NH];
__device__ float  g_pmax[QK_BLOCKS];
__device__ float  g_max;
__device__ __half g_xh[MROWS * CH];       // fp16 x
__device__ __half g_wh[4 * CH * CH];      // fp16 Wq|Wk|Wv|Wx

__device__ __forceinline__ void cp_async16(void* sptr, const void* gptr) {
    uint32_t sa = (uint32_t)__cvta_generic_to_shared(sptr);
    asm volatile("cp.async.cg.shared.global [%0], [%1], 16;" :: "r"(sa), "l"(gptr));
}
__device__ __forceinline__ void ldsm_x4(uint32_t addr, uint32_t& r0, uint32_t& r1,
                                        uint32_t& r2, uint32_t& r3) {
    asm volatile("ldmatrix.sync.aligned.m8n8.x4.shared.b16 {%0,%1,%2,%3}, [%4];"
                 : "=r"(r0), "=r"(r1), "=r"(r2), "=r"(r3) : "r"(addr));
}

// ============================================================
// elementwise fp32 -> fp16 conversion (pre-pass)
// ============================================================
__global__ __launch_bounds__(256) void cvt_half_kernel(
    const float4* __restrict__ src, __half2* __restrict__ dst, int n4)
{
    const int i = blockIdx.x * 256 + threadIdx.x;
    if (i < n4) {
        float4 v = src[i];
        dst[2 * i]     = __floats2half2_rn(v.x, v.y);
        dst[2 * i + 1] = __floats2half2_rn(v.z, v.w);
    }
}

// ============================================================
// FP16 tensor-core GEMM with bias (fp32 accum), double-buffered
// cp.async.  out[m,n] = sum_k A[m,k] * Wsel[nmod,k] + bsel[nmod]
// A: [M,K] half, W: [N,K] half row-major; weight/bias selected
// per 1024-col segment (fused qkv).  128x128x32 tile, 256 thr
// (8 warps 4x2, warp tile 32x64), mma.sync.m16n8k16.f16,
// smem row stride 40 halves -> conflict-free ldmatrix.
// ============================================================
__global__ __launch_bounds__(256) void hgemm_bias_kernel(
    const __half* __restrict__ A,
    const __half* __restrict__ W0, const __half* __restrict__ W1,
    const __half* __restrict__ W2,
    const float* __restrict__ b0, const float* __restrict__ b1,
    const float* __restrict__ b2,
    float* __restrict__ out, int N, int K)
{
    constexpr int ST = 40;                 // halves per smem row (32 + 8 pad)
    __shared__ __half As[2][128 * ST];
    __shared__ __half Bs[2][128 * ST];

    const int bm = blockIdx.y * 128;
    const int bn = blockIdx.x * 128;
    const int sel = bn >> 10;
    const __half* W = sel == 0 ? W0 : (sel == 1 ? W1 : W2);
    const float* bias = sel == 0 ? b0 : (sel == 1 ? b1 : b2);
    const int wbase = bn & 1023;

    const int t    = threadIdx.x;
    const int lane = t & 31;
    const int warp = t >> 5;
    const int gid  = lane >> 2;
    const int tig  = lane & 3;
    const int wm = (warp >> 1) * 32;
    const int wn = (warp & 1) * 64;

    // ldmatrix per-thread offsets (halves): row = lane&15, col8 = (lane>>4)*8
    const int lrow16 = lane & 15;
    const int lc8    = (lane >> 4) * 8;
    const uint32_t sAs = (uint32_t)__cvta_generic_to_shared(&As[0][0]);
    const uint32_t sBs = (uint32_t)__cvta_generic_to_shared(&Bs[0][0]);
    constexpr uint32_t BUFB = 128 * ST * 2;   // bytes per stage

    float c[2][8][4];
    #pragma unroll
    for (int mi = 0; mi < 2; mi++)
        #pragma unroll
        for (int ni = 0; ni < 8; ni++)
            #pragma unroll
            for (int r = 0; r < 4; r++) c[mi][ni][r] = 0.0f;

    // stage copy: 128 rows x 32 halves (64B) per operand = 512 16B chunks;
    // 2 chunks per thread per operand
    auto issue = [&](int k0, int st) {
        #pragma unroll
        for (int i = 0; i < 2; i++) {
            const int ch = t + i * 256;
            const int row = ch >> 2, c8 = (ch & 3) * 8;
            cp_async16(&As[st][row * ST + c8],
                       A + (size_t)(bm + row) * K + k0 + c8);
            cp_async16(&Bs[st][row * ST + c8],
                       W + (size_t)(wbase + row) * K + k0 + c8);
        }
        asm volatile("cp.async.commit_group;");
    };

    const int NSTEP = K / 32;
    issue(0, 0);

    for (int s = 0; s < NSTEP; s++) {
        const int buf = s & 1;
        if (s + 1 < NSTEP) {
            issue((s + 1) * 32, buf ^ 1);
            asm volatile("cp.async.wait_group 1;");
        } else {
            asm volatile("cp.async.wait_group 0;");
        }
        __syncthreads();

        #pragma unroll
        for (int ks = 0; ks < 32; ks += 16) {
            // A fragments: 2 x (16x16) via ldmatrix.x4
            uint32_t a[2][4];
            #pragma unroll
            for (int mi = 0; mi < 2; mi++) {
                const uint32_t addr = sAs + buf * BUFB +
                    ((wm + mi * 16 + lrow16) * ST + ks + lc8) * 2;
                ldsm_x4(addr, a[mi][0], a[mi][1], a[mi][2], a[mi][3]);
            }
            // B fragments: 4 x (16n x 16k) -> 8 n8-groups of 2 regs
            uint32_t b[8][2];
            #pragma unroll
            for (int ni2 = 0; ni2 < 4; ni2++) {
                uint32_t r0, r1, r2, r3;
                const uint32_t addr = sBs + buf * BUFB +
                    ((wn + ni2 * 16 + lrow16) * ST + ks + lc8) * 2;
                ldsm_x4(addr, r0, r1, r2, r3);
                b[2 * ni2][0] = r0;  b[2 * ni2][1] = r2;      // n rows 0-7
                b[2 * ni2 + 1][0] = r1;  b[2 * ni2 + 1][1] = r3;  // n rows 8-15
            }
            #pragma unroll
            for (int ni = 0; ni < 8; ni++)
                #pragma unroll
                for (int mi = 0; mi < 2; mi++) {
                    asm volatile(
                        "mma.sync.aligned.m16n8k16.row.col.f32.f16.f16.f32 "
                        "{%0,%1,%2,%3}, {%4,%5,%6,%7}, {%8,%9}, {%0,%1,%2,%3};"
                        : "+f"(c[mi][ni][0]), "+f"(c[mi][ni][1]),
                          "+f"(c[mi][ni][2]), "+f"(c[mi][ni][3])
                        : "r"(a[mi][0]), "r"(a[mi][1]), "r"(a[mi][2]), "r"(a[mi][3]),
                          "r"(b[ni][0]), "r"(b[ni][1]));
                }
        }
        __syncthreads();
    }

    // epilogue: c0/c1 = (row gid, cols tig*2..+1); c2/c3 = row gid+8
    #pragma unroll
    for (int mi = 0; mi < 2; mi++) {
        const int row = bm + wm + mi * 16 + gid;
        #pragma unroll
        for (int ni = 0; ni < 8; ni++) {
            const int col = bn + wn + ni * 8 + tig * 2;
            const float2 bv = *(const float2*)(bias + (wbase + wn + ni * 8 + tig * 2));
            *(float2*)(out + (size_t)row * N + col) =
                make_float2(c[mi][ni][0] + bv.x, c[mi][ni][1] + bv.y);
            *(float2*)(out + (size_t)(row + 8) * N + col) =
                make_float2(c[mi][ni][2] + bv.x, c[mi][ni][3] + bv.y);
        }
    }
}

// ============================================================
// Per-edge scaled dot products + per-block max.
// Block per (query qs, b): q row staged in smem once, 8 warps x
// 4 edges gather k rows. head = 2j + (lane>=16); xor-shuffle
// {1,2,4,8} reduces each 16-lane half.
// q_id = repeat(arange(S), EPQ) -> query = e >> 5.
// ============================================================
__global__ __launch_bounds__(256) void edge_qk_kernel(
    const float* __restrict__ qkv, const int* __restrict__ k_id,
    float* __restrict__ qk, float* __restrict__ pmax)
{
    __shared__ float4 qs4[CH / 4];
    __shared__ int ksm[EPQ];
    __shared__ float red[8];

    const int qs = blockIdx.x >> 1;
    const int b  = blockIdx.x & 1;
    const int t    = threadIdx.x;
    const int lane = t & 31;
    const int warp = t >> 5;
    const int ebase = qs * EPQ;

    qs4[t] = *((const float4*)(qkv + (size_t)(qs * NB + b) * QKV_N) + t);
    if (t < EPQ) ksm[t] = k_id[ebase + t];
    __syncthreads();

    float mloc = -3.4e38f;
    #pragma unroll
    for (int i = 0; i < 4; i++) {
        const int e = warp * 4 + i;
        const float4* kp = (const float4*)(
            qkv + (size_t)(ksm[e] * NB + b) * QKV_N + CH);
        float val[8];
        #pragma unroll
        for (int j = 0; j < 8; j++) {
            float4 a = qs4[j * 32 + lane];
            float4 cc = kp[j * 32 + lane];
            float p = a.x * cc.x + a.y * cc.y + a.z * cc.z + a.w * cc.w;
            p += __shfl_xor_sync(0xffffffffu, p, 1);
            p += __shfl_xor_sync(0xffffffffu, p, 2);
            p += __shfl_xor_sync(0xffffffffu, p, 4);
            p += __shfl_xor_sync(0xffffffffu, p, 8);
            p *= 0.125f;
            val[j] = p;
            mloc = fmaxf(mloc, p);
        }
        float* dst = qk + (size_t)((ebase + e) * NB + b) * NH;
        if (lane == 0) {
            #pragma unroll
            for (int j = 0; j < 8; j++) dst[2 * j] = val[j];
        } else if (lane == 16) {
            #pragma unroll
            for (int j = 0; j < 8; j++) dst[2 * j + 1] = val[j];
        }
    }

    mloc = fmaxf(mloc, __shfl_xor_sync(0xffffffffu, mloc, 16));
    if (lane == 0) red[warp] = mloc;
    __syncthreads();
    if (t == 0) {
        float m = red[0];
        #pragma unroll
        for (int w = 1; w < 8; w++) m = fmaxf(m, red[w]);
        pmax[blockIdx.x] = m;
    }
}

// ============================================================
// final max over partials (single block, deterministic)
// ============================================================
__global__ __launch_bounds__(256) void reduce_max_kernel(
    const float* __restrict__ pmax, int n, float* __restrict__ gmax)
{
    __shared__ float red[256];
    float m = -3.4e38f;
    for (int i = threadIdx.x; i < n; i += 256) m = fmaxf(m, pmax[i]);
    red[threadIdx.x] = m;
    __syncthreads();
    #pragma unroll
    for (int off = 128; off > 0; off >>= 1) {
        if (threadIdx.x < off)
            red[threadIdx.x] = fmaxf(red[threadIdx.x], red[threadIdx.x + off]);
        __syncthreads();
    }
    if (threadIdx.x == 0) *gmax = red[0];
}

// ============================================================
// Segment softmax + weighted value aggregation.
// Block per (s, b). Weights computed once in smem; 256 threads
// sweep 32 v rows with coalesced float4 loads. Output written as
// fp16 (input of the out-projection GEMM).
// ============================================================
__global__ __launch_bounds__(256) void aggregate_kernel(
    const float* __restrict__ qk, const float* __restrict__ qkv,
    const int* __restrict__ k_id, const float* __restrict__ gmax,
    __half* __restrict__ attn)
{
    __shared__ float sw[EPQ * NH];
    __shared__ float sinvd[NH];
    __shared__ int ksm[EPQ];

    const int s = blockIdx.x >> 1;
    const int b = blockIdx.x & 1;
    const int t = threadIdx.x;
    const int ebase = s * EPQ;
    const float mx = *gmax;

    if (t < EPQ) ksm[t] = k_id[ebase + t];
    #pragma unroll
    for (int i = 0; i < 2; i++) {
        const int idx = t + i * 256;
        const int e = idx >> 4, h = idx & 15;
        sw[idx] = expf(qk[(size_t)((ebase + e) * NB + b) * NH + h] - mx);
    }
    __syncthreads();
    if (t < NH) {
        float d = 0.0f;
        #pragma unroll
        for (int e = 0; e < EPQ; e++) d += sw[e * NH + t];
        sinvd[t] = 1.0f / d;
    }
    __syncthreads();

    const int h = t >> 4;
    float4 acc = make_float4(0.f, 0.f, 0.f, 0.f);
    #pragma unroll 4
    for (int e = 0; e < EPQ; e++) {
        const float w = sw[e * NH + h];
        const float4 vv = *((const float4*)(
            qkv + (size_t)(ksm[e] * NB + b) * QKV_N + 2 * CH) + t);
        acc.x += w * vv.x; acc.y += w * vv.y;
        acc.z += w * vv.z; acc.w += w * vv.w;
    }
    const float inv = sinvd[h];
    __half2* op = (__half2*)(attn + (size_t)(s * NB + b) * CH) + 2 * t;
    op[0] = __floats2half2_rn(acc.x * inv, acc.y * inv);
    op[1] = __floats2half2_rn(acc.z * inv, acc.w * inv);
}

// ============================================================
// host launcher (graph-capturable: kernel launches only)
// ============================================================
extern "C" void kernel_launch(void* const* d_in, const int* in_sizes, int n_in,
                              void* d_out, int out_size)
{
    const float* x   = (const float*)d_in[0];
    const int*  k_id = (const int*)d_in[2];
    const float* Wq  = (const float*)d_in[3];
    const float* bq  = (const float*)d_in[4];
    const float* Wk  = (const float*)d_in[5];
    const float* bk  = (const float*)d_in[6];
    const float* Wv  = (const float*)d_in[7];
    const float* bv  = (const float*)d_in[8];
    const float* Wx  = (const float*)d_in[9];
    const float* bx  = (const float*)d_in[10];
    float* out = (float*)d_out;

    float *qkv, *qkbuf, *pmax, *gmax;
    __half *attn, *xh, *wh;
    cudaGetSymbolAddress((void**)&qkv,   g_qkv);
    cudaGetSymbolAddress((void**)&attn,  g_attn);
    cudaGetSymbolAddress((void**)&qkbuf, g_qk);
    cudaGetSymbolAddress((void**)&pmax,  g_pmax);
    cudaGetSymbolAddress((void**)&gmax,  g_max);
    cudaGetSymbolAddress((void**)&xh,    g_xh);
    cudaGetSymbolAddress((void**)&wh,    g_wh);

    constexpr int WSZ = CH * CH;
    constexpr int XN4 = MROWS * CH / 4;
    constexpr int WN4 = WSZ / 4;

    // fp16 conversion pre-pass
    cvt_half_kernel<<<XN4 / 256, 256>>>((const float4*)x,  (__half2*)xh, XN4);
    cvt_half_kernel<<<WN4 / 256, 256>>>((const float4*)Wq, (__half2*)(wh + 0 * WSZ), WN4);
    cvt_half_kernel<<<WN4 / 256, 256>>>((const float4*)Wk, (__half2*)(wh + 1 * WSZ), WN4);
    cvt_half_kernel<<<WN4 / 256, 256>>>((const float4*)Wv, (__half2*)(wh + 2 * WSZ), WN4);
    cvt_half_kernel<<<WN4 / 256, 256>>>((const float4*)Wx, (__half2*)(wh + 3 * WSZ), WN4);

    // fused q/k/v projection: one GEMM, N=3072
    hgemm_bias_kernel<<<dim3(QKV_N / 128, MROWS / 128), 256>>>(
        xh, wh + 0 * WSZ, wh + 1 * WSZ, wh + 2 * WSZ, bq, bk, bv, qkv, QKV_N, CH);

    // per-edge dots + global max
    edge_qk_kernel<<<QK_BLOCKS, 256>>>(qkv, k_id, qkbuf, pmax);
    reduce_max_kernel<<<1, 256>>>(pmax, QK_BLOCKS, gmax);

    // segment softmax + V aggregation (writes fp16 attn)
    aggregate_kernel<<<QK_BLOCKS, 256>>>(qkbuf, qkv, k_id, gmax, attn);

    // output projection
    hgemm_bias_kernel<<<dim3(CH / 128, MROWS / 128), 256>>>(
        attn, wh + 3 * WSZ, wh + 3 * WSZ, wh + 3 * WSZ, bx, bx, bx, out, CH, CH);
}

// round 8
// speedup vs baseline: 5.6940x; 1.1930x over previous
#include <cuda_runtime.h>
#include <cuda_fp16.h>
#include <cstdint>

// Problem constants
constexpr int SEQ = 2048;
constexpr int NB  = 2;      // batch
constexpr int CH  = 1024;   // channels
constexpr int NH  = 16;     // heads
constexpr int EPQ = 32;     // edges per query
constexpr int MROWS = SEQ * NB;         // 4096 GEMM rows
constexpr int QKV_N = 3 * CH;           // 3072 fused projection cols
constexpr int ATT_BLOCKS = SEQ * NB;    // 4096 (block per (query, b))

// -------- device scratch (no allocations allowed) --------
__device__ __half g_qkvh[MROWS * QKV_N];  // q | k | v per row (fp16)
__device__ __half g_attn[MROWS * CH];     // attention output (fp16)
__device__ __half g_xh[MROWS * CH];       // fp16 x
__device__ __half g_wh[4 * CH * CH];      // fp16 Wq|Wk|Wv|Wx

__device__ __forceinline__ void cp_async16(void* sptr, const void* gptr) {
    uint32_t sa = (uint32_t)__cvta_generic_to_shared(sptr);
    asm volatile("cp.async.cg.shared.global [%0], [%1], 16;" :: "r"(sa), "l"(gptr));
}
__device__ __forceinline__ void ldsm_x4(uint32_t addr, uint32_t& r0, uint32_t& r1,
                                        uint32_t& r2, uint32_t& r3) {
    asm volatile("ldmatrix.sync.aligned.m8n8.x4.shared.b16 {%0,%1,%2,%3}, [%4];"
                 : "=r"(r0), "=r"(r1), "=r"(r2), "=r"(r3) : "r"(addr));
}

// ============================================================
// single fused fp32 -> fp16 conversion pre-pass:
// chunks [0, 2^20) = x ; [2^20, 2^21) = Wq|Wk|Wv|Wx (2^18 each)
// ============================================================
constexpr int WSZ = CH * CH;            // 1,048,576
constexpr int XN4 = MROWS * CH / 4;     // 1,048,576 = 2^20
constexpr int WN4 = WSZ / 4;            // 262,144  = 2^18
constexpr int CVT_CHUNKS = XN4 + 4 * WN4;   // 2^21

__global__ __launch_bounds__(256) void cvt_all_kernel(
    const float4* __restrict__ x,
    const float4* __restrict__ wq, const float4* __restrict__ wk,
    const float4* __restrict__ wv, const float4* __restrict__ wx,
    __half2* __restrict__ xh, __half2* __restrict__ wh)
{
    const int i = blockIdx.x * 256 + threadIdx.x;
    const float4* src;
    __half2* dst;
    if (i < XN4) {
        src = x + i;
        dst = xh + 2 * (size_t)i;
    } else {
        const int j = i - XN4;
        const int sel = j >> 18;
        const int off = j & (WN4 - 1);
        const float4* w = sel == 0 ? wq : (sel == 1 ? wk : (sel == 2 ? wv : wx));
        src = w + off;
        dst = wh + 2 * ((size_t)sel * WN4 + off);
    }
    float4 v = *src;
    dst[0] = __floats2half2_rn(v.x, v.y);
    dst[1] = __floats2half2_rn(v.z, v.w);
}

// ============================================================
// FP16 tensor-core GEMM with bias (fp32 accum), double-buffered
// cp.async.  out[m,n] = sum_k A[m,k] * Wsel[nmod,k] + bsel[nmod]
// Weight/bias selected per 1024-col segment (fused qkv).
// 128x128x32 tile, 256 thr (8 warps 4x2, warp tile 32x64),
// mma.sync.m16n8k16.f16, smem row stride 40 halves.
// OUT = __half (qkv) or float (final output).
// ============================================================
template <typename OUT>
__global__ __launch_bounds__(256) void hgemm_bias_kernel(
    const __half* __restrict__ A,
    const __half* __restrict__ W0, const __half* __restrict__ W1,
    const __half* __restrict__ W2,
    const float* __restrict__ b0, const float* __restrict__ b1,
    const float* __restrict__ b2,
    OUT* __restrict__ out, int N, int K)
{
    constexpr int ST = 40;
    __shared__ __half As[2][128 * ST];
    __shared__ __half Bs[2][128 * ST];

    const int bm = blockIdx.y * 128;
    const int bn = blockIdx.x * 128;
    const int sel = bn >> 10;
    const __half* W = sel == 0 ? W0 : (sel == 1 ? W1 : W2);
    const float* bias = sel == 0 ? b0 : (sel == 1 ? b1 : b2);
    const int wbase = bn & 1023;

    const int t    = threadIdx.x;
    const int lane = t & 31;
    const int warp = t >> 5;
    const int gid  = lane >> 2;
    const int tig  = lane & 3;
    const int wm = (warp >> 1) * 32;
    const int wn = (warp & 1) * 64;

    const int lrow16 = lane & 15;
    const int lc8    = (lane >> 4) * 8;
    const uint32_t sAs = (uint32_t)__cvta_generic_to_shared(&As[0][0]);
    const uint32_t sBs = (uint32_t)__cvta_generic_to_shared(&Bs[0][0]);
    constexpr uint32_t BUFB = 128 * ST * 2;

    float c[2][8][4];
    #pragma unroll
    for (int mi = 0; mi < 2; mi++)
        #pragma unroll
        for (int ni = 0; ni < 8; ni++)
            #pragma unroll
            for (int r = 0; r < 4; r++) c[mi][ni][r] = 0.0f;

    auto issue = [&](int k0, int st) {
        #pragma unroll
        for (int i = 0; i < 2; i++) {
            const int ch = t + i * 256;
            const int row = ch >> 2, c8 = (ch & 3) * 8;
            cp_async16(&As[st][row * ST + c8],
                       A + (size_t)(bm + row) * K + k0 + c8);
            cp_async16(&Bs[st][row * ST + c8],
                       W + (size_t)(wbase + row) * K + k0 + c8);
        }
        asm volatile("cp.async.commit_group;");
    };

    const int NSTEP = K / 32;
    issue(0, 0);

    for (int s = 0; s < NSTEP; s++) {
        const int buf = s & 1;
        if (s + 1 < NSTEP) {
            issue((s + 1) * 32, buf ^ 1);
            asm volatile("cp.async.wait_group 1;");
        } else {
            asm volatile("cp.async.wait_group 0;");
        }
        __syncthreads();

        #pragma unroll
        for (int ks = 0; ks < 32; ks += 16) {
            uint32_t a[2][4];
            #pragma unroll
            for (int mi = 0; mi < 2; mi++) {
                const uint32_t addr = sAs + buf * BUFB +
                    ((wm + mi * 16 + lrow16) * ST + ks + lc8) * 2;
                ldsm_x4(addr, a[mi][0], a[mi][1], a[mi][2], a[mi][3]);
            }
            uint32_t b[8][2];
            #pragma unroll
            for (int ni2 = 0; ni2 < 4; ni2++) {
                uint32_t r0, r1, r2, r3;
                const uint32_t addr = sBs + buf * BUFB +
                    ((wn + ni2 * 16 + lrow16) * ST + ks + lc8) * 2;
                ldsm_x4(addr, r0, r1, r2, r3);
                b[2 * ni2][0] = r0;      b[2 * ni2][1] = r2;
                b[2 * ni2 + 1][0] = r1;  b[2 * ni2 + 1][1] = r3;
            }
            #pragma unroll
            for (int ni = 0; ni < 8; ni++)
                #pragma unroll
                for (int mi = 0; mi < 2; mi++) {
                    asm volatile(
                        "mma.sync.aligned.m16n8k16.row.col.f32.f16.f16.f32 "
                        "{%0,%1,%2,%3}, {%4,%5,%6,%7}, {%8,%9}, {%0,%1,%2,%3};"
                        : "+f"(c[mi][ni][0]), "+f"(c[mi][ni][1]),
                          "+f"(c[mi][ni][2]), "+f"(c[mi][ni][3])
                        : "r"(a[mi][0]), "r"(a[mi][1]), "r"(a[mi][2]), "r"(a[mi][3]),
                          "r"(b[ni][0]), "r"(b[ni][1]));
                }
        }
        __syncthreads();
    }

    #pragma unroll
    for (int mi = 0; mi < 2; mi++) {
        const int row = bm + wm + mi * 16 + gid;
        #pragma unroll
        for (int ni = 0; ni < 8; ni++) {
            const int col = bn + wn + ni * 8 + tig * 2;
            const float2 bv = *(const float2*)(bias + (wbase + wn + ni * 8 + tig * 2));
            const float o0 = c[mi][ni][0] + bv.x, o1 = c[mi][ni][1] + bv.y;
            const float o2 = c[mi][ni][2] + bv.x, o3 = c[mi][ni][3] + bv.y;
            if constexpr (sizeof(OUT) == 2) {
                *(__half2*)((__half*)out + (size_t)row * N + col) =
                    __floats2half2_rn(o0, o1);
                *(__half2*)((__half*)out + (size_t)(row + 8) * N + col) =
                    __floats2half2_rn(o2, o3);
            } else {
                *(float2*)((float*)out + (size_t)row * N + col) = make_float2(o0, o1);
                *(float2*)((float*)out + (size_t)(row + 8) * N + col) = make_float2(o2, o3);
            }
        }
    }
}

// ============================================================
// FUSED sparse attention: block per (query s, b).
// num/d is invariant to the softmax shift, so a per-(s,b,h)
// LOCAL max replaces the reference's global max exactly (up to
// fp rounding) -> no global reduction, single kernel.
// Phase B: 8 warps x 4 edges compute 16-head dots (segmented
//          8-lane reduce; fp16 q/k, fp32 math).
// Phase C: per-head max -> exp -> denom in smem.
// Phase D: 256 threads sweep 32 fp16 v rows, coalesced.
// q_id = repeat(arange(S), EPQ) -> query = e >> 5.
// ============================================================
__global__ __launch_bounds__(256) void fused_attn_kernel(
    const __half* __restrict__ qkv, const int* __restrict__ k_id,
    __half* __restrict__ attn)
{
    __shared__ uint4 qrow[CH / 8];       // 1024 halves
    __shared__ float sw[EPQ * NH];       // logits -> weights
    __shared__ float smax[NH];
    __shared__ float sinvd[NH];
    __shared__ int ksm[EPQ];

    const int s = blockIdx.x >> 1;
    const int b = blockIdx.x & 1;
    const int t    = threadIdx.x;
    const int lane = t & 31;
    const int warp = t >> 5;
    const int ebase = s * EPQ;

    if (t < CH / 8)
        qrow[t] = *((const uint4*)(qkv + (size_t)(s * NB + b) * QKV_N) + t);
    if (t < EPQ) ksm[t] = k_id[ebase + t];
    __syncthreads();

    // ---- Phase B: dot products ----
    #pragma unroll
    for (int i = 0; i < 4; i++) {
        const int e = warp * 4 + i;
        const uint4* kp = (const uint4*)(
            qkv + (size_t)(ksm[e] * NB + b) * QKV_N + CH);
        #pragma unroll
        for (int it = 0; it < 4; it++) {
            const uint4 qa = qrow[it * 32 + lane];
            const uint4 ka = kp[it * 32 + lane];
            float p = 0.0f;
            {
                const __half2* qh = (const __half2*)&qa;
                const __half2* kh = (const __half2*)&ka;
                #pragma unroll
                for (int u = 0; u < 4; u++) {
                    const float2 qf = __half22float2(qh[u]);
                    const float2 kf = __half22float2(kh[u]);
                    p += qf.x * kf.x + qf.y * kf.y;
                }
            }
            // segmented reduce within each 8-lane group (one head each)
            p += __shfl_xor_sync(0xffffffffu, p, 1);
            p += __shfl_xor_sync(0xffffffffu, p, 2);
            p += __shfl_xor_sync(0xffffffffu, p, 4);
            if ((lane & 7) == 0)
                sw[e * NH + it * 4 + (lane >> 3)] = p * 0.125f;  // 1/sqrt(64)
        }
    }
    __syncthreads();

    // ---- Phase C: per-head max, exp, denom ----
    if (t < NH) {
        float m = sw[t];
        #pragma unroll
        for (int e = 1; e < EPQ; e++) m = fmaxf(m, sw[e * NH + t]);
        smax[t] = m;
    }
    __syncthreads();
    #pragma unroll
    for (int i = 0; i < 2; i++) {
        const int idx = t + i * 256;
        sw[idx] = expf(sw[idx] - smax[idx & 15]);
    }
    __syncthreads();
    if (t < NH) {
        float d = 0.0f;
        #pragma unroll
        for (int e = 0; e < EPQ; e++) d += sw[e * NH + t];
        sinvd[t] = 1.0f / d;
    }
    __syncthreads();

    // ---- Phase D: weighted V sweep (4 channels per thread) ----
    const int h = t >> 4;
    float4 acc = make_float4(0.f, 0.f, 0.f, 0.f);
    #pragma unroll 4
    for (int e = 0; e < EPQ; e++) {
        const float w = sw[e * NH + h];
        const uint2 vr = *((const uint2*)(
            qkv + (size_t)(ksm[e] * NB + b) * QKV_N + 2 * CH) + t);
        const float2 v0 = __half22float2(*(const __half2*)&vr.x);
        const float2 v1 = __half22float2(*(const __half2*)&vr.y);
        acc.x += w * v0.x; acc.y += w * v0.y;
        acc.z += w * v1.x; acc.w += w * v1.y;
    }
    const float inv = sinvd[h];
    __half2* op = (__half2*)(attn + (size_t)(s * NB + b) * CH) + 2 * t;
    op[0] = __floats2half2_rn(acc.x * inv, acc.y * inv);
    op[1] = __floats2half2_rn(acc.z * inv, acc.w * inv);
}

// ============================================================
// host launcher (graph-capturable: kernel launches only)
// ============================================================
extern "C" void kernel_launch(void* const* d_in, const int* in_sizes, int n_in,
                              void* d_out, int out_size)
{
    const float* x   = (const float*)d_in[0];
    const int*  k_id = (const int*)d_in[2];
    const float* Wq  = (const float*)d_in[3];
    const float* bq  = (const float*)d_in[4];
    const float* Wk  = (const float*)d_in[5];
    const float* bk  = (const float*)d_in[6];
    const float* Wv  = (const float*)d_in[7];
    const float* bv  = (const float*)d_in[8];
    const float* Wx  = (const float*)d_in[9];
    const float* bx  = (const float*)d_in[10];
    float* out = (float*)d_out;

    __half *qkvh, *attn, *xh, *wh;
    cudaGetSymbolAddress((void**)&qkvh, g_qkvh);
    cudaGetSymbolAddress((void**)&attn, g_attn);
    cudaGetSymbolAddress((void**)&xh,   g_xh);
    cudaGetSymbolAddress((void**)&wh,   g_wh);

    // fused fp16 conversion pre-pass (x + all 4 weights, one launch)
    cvt_all_kernel<<<CVT_CHUNKS / 256, 256>>>(
        (const float4*)x, (const float4*)Wq, (const float4*)Wk,
        (const float4*)Wv, (const float4*)Wx, (__half2*)xh, (__half2*)wh);

    // fused q/k/v projection: one GEMM, N=3072, fp16 output
    hgemm_bias_kernel<__half><<<dim3(QKV_N / 128, MROWS / 128), 256>>>(
        xh, wh + 0 * WSZ, wh + 1 * WSZ, wh + 2 * WSZ, bq, bk, bv, qkvh, QKV_N, CH);

    // fused edge dots + local-max softmax + V aggregation
    fused_attn_kernel<<<ATT_BLOCKS, 256>>>(qkvh, k_id, attn);

    // output projection, fp32 output
    hgemm_bias_kernel<float><<<dim3(CH / 128, MROWS / 128), 256>>>(
        attn, wh + 3 * WSZ, wh + 3 * WSZ, wh + 3 * WSZ, bx, bx, bx, out, CH, CH);
}

// round 11
// speedup vs baseline: 6.3022x; 1.1068x over previous
#include <cuda_runtime.h>
#include <cuda_fp16.h>
#include <cstdint>

// Problem constants
constexpr int SEQ = 2048;
constexpr int NB  = 2;      // batch
constexpr int CH  = 1024;   // channels
constexpr int NH  = 16;     // heads
constexpr int EPQ = 32;     // edges per query
constexpr int MROWS = SEQ * NB;         // 4096 GEMM rows
constexpr int QKV_N = 3 * CH;           // 3072 fused projection cols
constexpr int ATT_BLOCKS = SEQ * NB;    // 4096 (block per (query, b))

// GEMM smem geometry
constexpr int GBK = 64;
constexpr int GST = 72;                         // 64 + 8 pad halves
constexpr int GEMM_STAGE = 128 * GST * 2;       // bytes per operand per stage
constexpr int GEMM_SMEM = 2 * 2 * GEMM_STAGE;   // 73,728 B (dynamic)

// -------- device scratch (no allocations allowed) --------
__device__ __half g_qkvh[MROWS * QKV_N];  // q | k | v per row (fp16)
__device__ __half g_attn[MROWS * CH];     // attention output (fp16)
__device__ __half g_xh[MROWS * CH];       // fp16 x
__device__ __half g_wh[4 * CH * CH];      // fp16 Wq|Wk|Wv|Wx

__device__ __forceinline__ void cp_async16(uint32_t sptr, const void* gptr) {
    asm volatile("cp.async.cg.shared.global [%0], [%1], 16;" :: "r"(sptr), "l"(gptr));
}
__device__ __forceinline__ void ldsm_x4(uint32_t addr, uint32_t& r0, uint32_t& r1,
                                        uint32_t& r2, uint32_t& r3) {
    asm volatile("ldmatrix.sync.aligned.m8n8.x4.shared.b16 {%0,%1,%2,%3}, [%4];"
                 : "=r"(r0), "=r"(r1), "=r"(r2), "=r"(r3) : "r"(addr));
}

// ============================================================
// single fused fp32 -> fp16 conversion pre-pass:
// chunks [0, 2^20) = x ; [2^20, 2^21) = Wq|Wk|Wv|Wx (2^18 each)
// ============================================================
constexpr int WSZ = CH * CH;            // 1,048,576
constexpr int XN4 = MROWS * CH / 4;     // 2^20
constexpr int WN4 = WSZ / 4;            // 2^18
constexpr int CVT_CHUNKS = XN4 + 4 * WN4;   // 2^21

__global__ __launch_bounds__(256) void cvt_all_kernel(
    const float4* __restrict__ x,
    const float4* __restrict__ wq, const float4* __restrict__ wk,
    const float4* __restrict__ wv, const float4* __restrict__ wx,
    __half2* __restrict__ xh, __half2* __restrict__ wh)
{
    const int i = blockIdx.x * 256 + threadIdx.x;
    const float4* src;
    __half2* dst;
    if (i < XN4) {
        src = x + i;
        dst = xh + 2 * (size_t)i;
    } else {
        const int j = i - XN4;
        const int sel = j >> 18;
        const int off = j & (WN4 - 1);
        const float4* w = sel == 0 ? wq : (sel == 1 ? wk : (sel == 2 ? wv : wx));
        src = w + off;
        dst = wh + 2 * ((size_t)sel * WN4 + off);
    }
    float4 v = *src;
    dst[0] = __floats2half2_rn(v.x, v.y);
    dst[1] = __floats2half2_rn(v.z, v.w);
}

// ============================================================
// FP16 tensor-core GEMM with bias (fp32 accum).
//   out[m,n] = sum_k A[m,k] * Wsel[nmod,k] + bsel[nmod]
// 128x128x64 tile (16 sync points), double-buffered cp.async,
// fragment-level ldsm/mma double buffering, 256 thr (8 warps
// 4x2, warp tile 32x64), mma.sync.m16n8k16.f16, smem row stride
// 72 halves (conflict-free ldsm). DYNAMIC smem (73,728 B) —
// layout: As[2][128*GST] | Bs[2][128*GST]. 2 CTAs/SM pinned.
// OUT = __half (qkv) or float (final out).
// ============================================================
template <typename OUT>
__global__ __launch_bounds__(256, 2) void hgemm_bias_kernel(
    const __half* __restrict__ A,
    const __half* __restrict__ W0, const __half* __restrict__ W1,
    const __half* __restrict__ W2,
    const float* __restrict__ b0, const float* __restrict__ b1,
    const float* __restrict__ b2,
    OUT* __restrict__ out, int N, int K)
{
    extern __shared__ __half smem[];
    __half* Asm = smem;                       // 2 stages
    __half* Bsm = smem + 2 * 128 * GST;       // 2 stages

    const int bm = blockIdx.y * 128;
    const int bn = blockIdx.x * 128;
    const int sel = bn >> 10;
    const __half* W = sel == 0 ? W0 : (sel == 1 ? W1 : W2);
    const float* bias = sel == 0 ? b0 : (sel == 1 ? b1 : b2);
    const int wbase = bn & 1023;

    const int t    = threadIdx.x;
    const int lane = t & 31;
    const int warp = t >> 5;
    const int gid  = lane >> 2;
    const int tig  = lane & 3;
    const int wm = (warp >> 1) * 32;
    const int wn = (warp & 1) * 64;

    const int lrow16 = lane & 15;
    const int lc8    = (lane >> 4) * 8;
    const uint32_t sAs = (uint32_t)__cvta_generic_to_shared(Asm);
    const uint32_t sBs = (uint32_t)__cvta_generic_to_shared(Bsm);
    constexpr uint32_t BUFB = 128 * GST * 2;   // bytes per stage

    float c[2][8][4];
    #pragma unroll
    for (int mi = 0; mi < 2; mi++)
        #pragma unroll
        for (int ni = 0; ni < 8; ni++)
            #pragma unroll
            for (int r = 0; r < 4; r++) c[mi][ni][r] = 0.0f;

    // stage copy: 128 rows x 64 halves (128B) per operand =
    // 1024 16B chunks; 4 chunks per thread per operand
    auto issue = [&](int k0, int st) {
        #pragma unroll
        for (int i = 0; i < 4; i++) {
            const int ch = t + i * 256;          // 0..1023
            const int row = ch >> 3, c8 = (ch & 7) * 8;
            cp_async16(sAs + st * BUFB + (row * GST + c8) * 2,
                       A + (size_t)(bm + row) * K + k0 + c8);
            cp_async16(sBs + st * BUFB + (row * GST + c8) * 2,
                       W + (size_t)(wbase + row) * K + k0 + c8);
        }
        asm volatile("cp.async.commit_group;");
    };

    // fragment load for one kstep (16 wide)
    auto load_frags = [&](uint32_t aB, uint32_t bB, int ks,
                          uint32_t a[2][4], uint32_t b[8][2]) {
        #pragma unroll
        for (int mi = 0; mi < 2; mi++)
            ldsm_x4(aB + ((wm + mi * 16 + lrow16) * GST + ks + lc8) * 2,
                    a[mi][0], a[mi][1], a[mi][2], a[mi][3]);
        #pragma unroll
        for (int ni2 = 0; ni2 < 4; ni2++) {
            uint32_t r0, r1, r2, r3;
            ldsm_x4(bB + ((wn + ni2 * 16 + lrow16) * GST + ks + lc8) * 2,
                    r0, r1, r2, r3);
            b[2 * ni2][0] = r0;      b[2 * ni2][1] = r2;
            b[2 * ni2 + 1][0] = r1;  b[2 * ni2 + 1][1] = r3;
        }
    };
    auto do_mma = [&](uint32_t a[2][4], uint32_t b[8][2]) {
        #pragma unroll
        for (int ni = 0; ni < 8; ni++)
            #pragma unroll
            for (int mi = 0; mi < 2; mi++) {
                asm volatile(
                    "mma.sync.aligned.m16n8k16.row.col.f32.f16.f16.f32 "
                    "{%0,%1,%2,%3}, {%4,%5,%6,%7}, {%8,%9}, {%0,%1,%2,%3};"
                    : "+f"(c[mi][ni][0]), "+f"(c[mi][ni][1]),
                      "+f"(c[mi][ni][2]), "+f"(c[mi][ni][3])
                    : "r"(a[mi][0]), "r"(a[mi][1]), "r"(a[mi][2]), "r"(a[mi][3]),
                      "r"(b[ni][0]), "r"(b[ni][1]));
            }
    };

    const int NSTEP = K / GBK;                 // 16
    issue(0, 0);

    for (int s = 0; s < NSTEP; s++) {
        const int buf = s & 1;
        if (s + 1 < NSTEP) {
            issue((s + 1) * GBK, buf ^ 1);
            asm volatile("cp.async.wait_group 1;");
        } else {
            asm volatile("cp.async.wait_group 0;");
        }
        __syncthreads();

        const uint32_t aB = sAs + buf * BUFB;
        const uint32_t bB = sBs + buf * BUFB;

        // software-pipelined ksteps: load next frags during mma
        uint32_t a0[2][4], b0r[8][2], a1[2][4], b1r[8][2];
        load_frags(aB, bB, 0, a0, b0r);
        load_frags(aB, bB, 16, a1, b1r);
        do_mma(a0, b0r);
        load_frags(aB, bB, 32, a0, b0r);
        do_mma(a1, b1r);
        load_frags(aB, bB, 48, a1, b1r);
        do_mma(a0, b0r);
        do_mma(a1, b1r);
        __syncthreads();
    }

    #pragma unroll
    for (int mi = 0; mi < 2; mi++) {
        const int row = bm + wm + mi * 16 + gid;
        #pragma unroll
        for (int ni = 0; ni < 8; ni++) {
            const int col = bn + wn + ni * 8 + tig * 2;
            const float2 bv = *(const float2*)(bias + (wbase + wn + ni * 8 + tig * 2));
            const float o0 = c[mi][ni][0] + bv.x, o1 = c[mi][ni][1] + bv.y;
            const float o2 = c[mi][ni][2] + bv.x, o3 = c[mi][ni][3] + bv.y;
            if constexpr (sizeof(OUT) == 2) {
                *(__half2*)((__half*)out + (size_t)row * N + col) =
                    __floats2half2_rn(o0, o1);
                *(__half2*)((__half*)out + (size_t)(row + 8) * N + col) =
                    __floats2half2_rn(o2, o3);
            } else {
                *(float2*)((float*)out + (size_t)row * N + col) = make_float2(o0, o1);
                *(float2*)((float*)out + (size_t)(row + 8) * N + col) = make_float2(o2, o3);
            }
        }
    }
}

// ============================================================
// FUSED sparse attention: block per (query s, b).
// num/d invariant to softmax shift -> per-(s,b,h) local max,
// no global reduction. Phases: dots -> max/exp/denom -> V sweep.
// q_id = repeat(arange(S), EPQ) -> query = e >> 5.
// ============================================================
__global__ __launch_bounds__(256) void fused_attn_kernel(
    const __half* __restrict__ qkv, const int* __restrict__ k_id,
    __half* __restrict__ attn)
{
    __shared__ uint4 qrow[CH / 8];
    __shared__ float sw[EPQ * NH];
    __shared__ float smax[NH];
    __shared__ float sinvd[NH];
    __shared__ int ksm[EPQ];

    const int s = blockIdx.x >> 1;
    const int b = blockIdx.x & 1;
    const int t    = threadIdx.x;
    const int lane = t & 31;
    const int warp = t >> 5;
    const int ebase = s * EPQ;

    if (t < CH / 8)
        qrow[t] = *((const uint4*)(qkv + (size_t)(s * NB + b) * QKV_N) + t);
    if (t < EPQ) ksm[t] = k_id[ebase + t];
    __syncthreads();

    #pragma unroll
    for (int i = 0; i < 4; i++) {
        const int e = warp * 4 + i;
        const uint4* kp = (const uint4*)(
            qkv + (size_t)(ksm[e] * NB + b) * QKV_N + CH);
        #pragma unroll
        for (int it = 0; it < 4; it++) {
            const uint4 qa = qrow[it * 32 + lane];
            const uint4 ka = kp[it * 32 + lane];
            float p = 0.0f;
            {
                const __half2* qh = (const __half2*)&qa;
                const __half2* kh = (const __half2*)&ka;
                #pragma unroll
                for (int u = 0; u < 4; u++) {
                    const float2 qf = __half22float2(qh[u]);
                    const float2 kf = __half22float2(kh[u]);
                    p += qf.x * kf.x + qf.y * kf.y;
                }
            }
            p += __shfl_xor_sync(0xffffffffu, p, 1);
            p += __shfl_xor_sync(0xffffffffu, p, 2);
            p += __shfl_xor_sync(0xffffffffu, p, 4);
            if ((lane & 7) == 0)
                sw[e * NH + it * 4 + (lane >> 3)] = p * 0.125f;
        }
    }
    __syncthreads();

    if (t < NH) {
        float m = sw[t];
        #pragma unroll
        for (int e = 1; e < EPQ; e++) m = fmaxf(m, sw[e * NH + t]);
        smax[t] = m;
    }
    __syncthreads();
    #pragma unroll
    for (int i = 0; i < 2; i++) {
        const int idx = t + i * 256;
        sw[idx] = expf(sw[idx] - smax[idx & 15]);
    }
    __syncthreads();
    if (t < NH) {
        float d = 0.0f;
        #pragma unroll
        for (int e = 0; e < EPQ; e++) d += sw[e * NH + t];
        sinvd[t] = 1.0f / d;
    }
    __syncthreads();

    const int h = t >> 4;
    float4 acc = make_float4(0.f, 0.f, 0.f, 0.f);
    #pragma unroll 4
    for (int e = 0; e < EPQ; e++) {
        const float w = sw[e * NH + h];
        const uint2 vr = *((const uint2*)(
            qkv + (size_t)(ksm[e] * NB + b) * QKV_N + 2 * CH) + t);
        const float2 v0 = __half22float2(*(const __half2*)&vr.x);
        const float2 v1 = __half22float2(*(const __half2*)&vr.y);
        acc.x += w * v0.x; acc.y += w * v0.y;
        acc.z += w * v1.x; acc.w += w * v1.y;
    }
    const float inv = sinvd[h];
    __half2* op = (__half2*)(attn + (size_t)(s * NB + b) * CH) + 2 * t;
    op[0] = __floats2half2_rn(acc.x * inv, acc.y * inv);
    op[1] = __floats2half2_rn(acc.z * inv, acc.w * inv);
}

// ============================================================
// host launcher (graph-capturable: kernel launches only)
// ============================================================
extern "C" void kernel_launch(void* const* d_in, const int* in_sizes, int n_in,
                              void* d_out, int out_size)
{
    const float* x   = (const float*)d_in[0];
    const int*  k_id = (const int*)d_in[2];
    const float* Wq  = (const float*)d_in[3];
    const float* bq  = (const float*)d_in[4];
    const float* Wk  = (const float*)d_in[5];
    const float* bk  = (const float*)d_in[6];
    const float* Wv  = (const float*)d_in[7];
    const float* bv  = (const float*)d_in[8];
    const float* Wx  = (const float*)d_in[9];
    const float* bx  = (const float*)d_in[10];
    float* out = (float*)d_out;

    __half *qkvh, *attn, *xh, *wh;
    cudaGetSymbolAddress((void**)&qkvh, g_qkvh);
    cudaGetSymbolAddress((void**)&attn, g_attn);
    cudaGetSymbolAddress((void**)&xh,   g_xh);
    cudaGetSymbolAddress((void**)&wh,   g_wh);

    // idempotent host-side attribute set (no device state, capture-legal)
    cudaFuncSetAttribute(hgemm_bias_kernel<__half>,
                         cudaFuncAttributeMaxDynamicSharedMemorySize, GEMM_SMEM);
    cudaFuncSetAttribute(hgemm_bias_kernel<float>,
                         cudaFuncAttributeMaxDynamicSharedMemorySize, GEMM_SMEM);

    // fused fp16 conversion pre-pass
    cvt_all_kernel<<<CVT_CHUNKS / 256, 256>>>(
        (const float4*)x, (const float4*)Wq, (const float4*)Wk,
        (const float4*)Wv, (const float4*)Wx, (__half2*)xh, (__half2*)wh);

    // fused q/k/v projection: one GEMM, N=3072, fp16 output
    hgemm_bias_kernel<__half><<<dim3(QKV_N / 128, MROWS / 128), 256, GEMM_SMEM>>>(
        xh, wh + 0 * WSZ, wh + 1 * WSZ, wh + 2 * WSZ, bq, bk, bv, qkvh, QKV_N, CH);

    // fused edge dots + local-max softmax + V aggregation
    fused_attn_kernel<<<ATT_BLOCKS, 256>>>(qkvh, k_id, attn);

    // output projection, fp32 output
    hgemm_bias_kernel<float><<<dim3(CH / 128, MROWS / 128), 256, GEMM_SMEM>>>(
        attn, wh + 3 * WSZ, wh + 3 * WSZ, wh + 3 * WSZ, bx, bx, bx, out, CH, CH);
}